// round 6
// baseline (speedup 1.0000x reference)
#include <cuda_runtime.h>
#include <math.h>
#include <float.h>

#define S_    3000
#define F_    6
#define N_    128
#define L_    40
#define LMAX_ 10
#define K_    5
#define SL_   (S_*LMAX_)   // 30000
#define NTILE_ 469         // ceil(30000/64)
#define NSPLIT_ 6
#define TILES_PER_SPLIT_ 79
#define NS5_  (NSPLIT_*K_) // 30
#define NSTK_ 20           // stocks per LSTM block
#define NBLK_ 150          // 150*20 = 3000
#define NPAIR_ (NSTK_/2)   // 10

typedef unsigned long long u64;

// ---------------- f32x2 packed-FMA helpers (sm_100+) ------------------------
__device__ __forceinline__ u64 pk2(float lo, float hi){
    u64 r;
    asm("mov.b64 %0,{%1,%2};" : "=l"(r)
        : "r"(__float_as_uint(lo)), "r"(__float_as_uint(hi)));
    return r;
}
__device__ __forceinline__ u64 dup2(float v){ return pk2(v, v); }
__device__ __forceinline__ float2 upk2(u64 v){
    unsigned lo, hi;
    asm("mov.b64 {%0,%1},%2;" : "=r"(lo), "=r"(hi) : "l"(v));
    float2 f; f.x = __uint_as_float(lo); f.y = __uint_as_float(hi); return f;
}
__device__ __forceinline__ void fma2(u64& d, u64 a, u64 b){
    asm("fma.rn.f32x2 %0,%1,%2,%0;" : "+l"(d) : "l"(a), "l"(b));
}
// load two adjacent u64s (one LDS.128) from shared memory
__device__ __forceinline__ void lds2u64(u64& a, u64& b, const float* p){
    unsigned ad = (unsigned)__cvta_generic_to_shared(p);
    asm("ld.shared.v2.u64 {%0,%1},[%2];" : "=l"(a), "=l"(b) : "r"(ad));
}

// ---------------- cp.async helpers ------------------------------------------
__device__ __forceinline__ void cp16(float* dst, const float* src, bool valid){
    unsigned d = (unsigned)__cvta_generic_to_shared(dst);
    int sz = valid ? 16 : 0;
    asm volatile("cp.async.cg.shared.global [%0], [%1], 16, %2;"
                 :: "r"(d), "l"(src), "r"(sz));
}
__device__ __forceinline__ void cp_commit(){
    asm volatile("cp.async.commit_group;" ::: "memory");
}

// ---------------- scratch (device globals; no allocations allowed) ----------
__device__ u64   g_Whh2[128*256];        // [k][256] u64 = packed col-pairs of Whh^T
__device__ float g_Hln[SL_*N_];          // [30000][128] layernormed H, t in [30,40)
__device__ float g_Hk [SL_*N_];          // l2norm(Hln @ WK^T)
__device__ float g_q  [S_*N_];           // l2norm(Hln[tgt,9] @ WQ^T)
__device__ float g_pval[S_*40];          // 6 splits x top5 per target
__device__ int   g_pidx[S_*40];

__device__ __forceinline__ float sigf(float x){ return 1.f/(1.f+__expf(-x)); }
__device__ __forceinline__ float tanhfast(float x){ return 2.f/(1.f+__expf(-2.f*x)) - 1.f; }
__device__ __forceinline__ bool better(float v,int i,float bv,int bi){
    return (v>bv) || (v==bv && i<bi);
}

// ---------------- kernel 0: pack Whh -> g_Whh2 [k][j] = (Whh[2j][k],Whh[2j+1][k])
__global__ void __launch_bounds__(256) pack_whh(const float* __restrict__ Whh){
    int idx = blockIdx.x*256 + threadIdx.x;          // 32768 elements
    if (idx < 128*256){
        int k = idx >> 8, j = idx & 255;
        g_Whh2[idx] = pk2(Whh[(2*j)*128 + k], Whh[(2*j+1)*128 + k]);
    }
}

// ---------------- kernel 1: LSTM (+ fused LayerNorm for t>=30) --------------
// 20 stocks per block, 256 threads, 150 blocks (one wave on 148 SMs).
// GEMM phase: thread owns 2 gate cols (j0=2*tid) for ALL 20 stocks
//   (acc packed over stock pairs). Whh read ONCE per block per step.
// Update phase: su = tid>>3 (<20), 16 units n0=(tid&7)*16, width-8 shfl LN.
__global__ void __launch_bounds__(256,1) lstm_kernel(
    const float* __restrict__ X,   const float* __restrict__ Wih,
    const float* __restrict__ bih, const float* __restrict__ bhh,
    const float* __restrict__ lng, const float* __restrict__ lnb)
{
    __shared__ float shT[128*22];          // h transposed: [k][stock], pad 22
    __shared__ float sg[NSTK_][516];       // gates [stock][512+pad]
    __shared__ u64   sx2[240*NPAIR_];      // x packed stock-pairs: [t*6+f][pair]
    const int tid = threadIdx.x;
    const int bs0 = blockIdx.x*NSTK_;

    // pack x into stock-pair u64s
    for (int idx = tid; idx < 240*NPAIR_; idx += 256){
        int tf = idx/NPAIR_, p = idx - tf*NPAIR_;
        sx2[tf*NPAIR_ + p] = pk2(X[(bs0 + 2*p)*240 + tf], X[(bs0 + 2*p+1)*240 + tf]);
    }
    for (int idx = tid; idx < 128*22; idx += 256) shT[idx] = 0.f;

    const int j0 = tid*2;                // gate cols j0, j0+1
    u64 wih_d[2][6];
    #pragma unroll
    for (int c=0;c<2;c++)
        #pragma unroll
        for (int f=0;f<6;f++) wih_d[c][f] = dup2(Wih[(j0+c)*6 + f]);
    u64 bias_d[2];
    bias_d[0] = dup2(bih[j0]   + bhh[j0]);
    bias_d[1] = dup2(bih[j0+1] + bhh[j0+1]);

    // update-phase mapping
    const int su = tid >> 3;             // 0..31 (active if <20)
    const int n0 = (tid & 7)*16;         // unit base, 16 units
    float cst[16];
    #pragma unroll
    for (int u=0;u<16;u++) cst[u]=0.f;
    float4 lg4[4], lb4[4];
    if (su < NSTK_){
        #pragma unroll
        for (int q=0;q<4;q++){
            lg4[q] = *(const float4*)&lng[n0+q*4];
            lb4[q] = *(const float4*)&lnb[n0+q*4];
        }
    }

    for (int t=0; t<40; t++){
        __syncthreads();
        // ---- gate GEMM: acc[pair][col], lanes = stocks (2p, 2p+1)
        u64 acc[NPAIR_][2];
        #pragma unroll
        for (int p=0;p<NPAIR_;p++){ acc[p][0]=bias_d[0]; acc[p][1]=bias_d[1]; }
        #pragma unroll
        for (int f=0;f<6;f++){
            u64 w0 = wih_d[0][f], w1 = wih_d[1][f];
            #pragma unroll
            for (int p=0;p<NPAIR_;p++){
                u64 xp = sx2[(t*6+f)*NPAIR_ + p];
                fma2(acc[p][0], xp, w0);
                fma2(acc[p][1], xp, w1);
            }
        }
        #pragma unroll 2
        for (int k4=0; k4<32; k4++){
            u64 w2[4];
            #pragma unroll
            for (int kk=0;kk<4;kk++)
                w2[kk] = g_Whh2[(k4*4+kk)*256 + tid];
            #pragma unroll
            for (int kk=0;kk<4;kk++){
                int k = k4*4+kk;
                float2 wf = upk2(w2[kk]);
                u64 wd0 = dup2(wf.x), wd1 = dup2(wf.y);
                #pragma unroll
                for (int p=0;p<NPAIR_;p++){
                    u64 hp = *(const u64*)&shT[k*22 + 2*p];
                    fma2(acc[p][0], hp, wd0);
                    fma2(acc[p][1], hp, wd1);
                }
            }
        }
        #pragma unroll
        for (int p=0;p<NPAIR_;p++){
            float2 a0 = upk2(acc[p][0]);   // col j0: stocks 2p, 2p+1
            float2 a1 = upk2(acc[p][1]);   // col j0+1
            sg[2*p  ][j0  ] = a0.x;
            sg[2*p+1][j0  ] = a0.y;
            sg[2*p  ][j0+1] = a1.x;
            sg[2*p+1][j0+1] = a1.y;
        }
        __syncthreads();

        // ---- cell update (threads with su < 20)
        if (su < NSTK_){
            float hval[16];
            #pragma unroll
            for (int q=0;q<4;q++){
                float4 gi = *(const float4*)&sg[su][     n0+q*4];
                float4 gf = *(const float4*)&sg[su][128+ n0+q*4];
                float4 gg = *(const float4*)&sg[su][256+ n0+q*4];
                float4 go = *(const float4*)&sg[su][384+ n0+q*4];
                float c0 = sigf(gf.x)*cst[q*4+0] + sigf(gi.x)*tanhfast(gg.x);
                float c1 = sigf(gf.y)*cst[q*4+1] + sigf(gi.y)*tanhfast(gg.y);
                float c2 = sigf(gf.z)*cst[q*4+2] + sigf(gi.z)*tanhfast(gg.z);
                float c3 = sigf(gf.w)*cst[q*4+3] + sigf(gi.w)*tanhfast(gg.w);
                cst[q*4+0]=c0; cst[q*4+1]=c1; cst[q*4+2]=c2; cst[q*4+3]=c3;
                hval[q*4+0] = sigf(go.x)*tanhfast(c0);
                hval[q*4+1] = sigf(go.y)*tanhfast(c1);
                hval[q*4+2] = sigf(go.z)*tanhfast(c2);
                hval[q*4+3] = sigf(go.w)*tanhfast(c3);
            }
            // write transposed h for next step's GEMM
            #pragma unroll
            for (int u=0;u<16;u++)
                shT[(n0+u)*22 + su] = hval[u];

            if (t >= 30){
                float sum = 0.f, ssq = 0.f;
                #pragma unroll
                for (int u=0;u<16;u++){ sum += hval[u]; ssq += hval[u]*hval[u]; }
                #pragma unroll
                for (int o=4;o>=1;o>>=1){
                    sum += __shfl_xor_sync(0xffffffffu, sum, o, 8);
                    ssq += __shfl_xor_sync(0xffffffffu, ssq, o, 8);
                }
                float mean = sum*(1.f/128.f);
                float var  = ssq*(1.f/128.f) - mean*mean;
                float rstd = rsqrtf(var + 1e-5f);
                float* dst = &g_Hln[((bs0+su)*10 + (t-30))*128 + n0];
                #pragma unroll
                for (int q=0;q<4;q++){
                    float4 o4;
                    o4.x = (hval[q*4+0]-mean)*rstd*lg4[q].x + lb4[q].x;
                    o4.y = (hval[q*4+1]-mean)*rstd*lg4[q].y + lb4[q].y;
                    o4.z = (hval[q*4+2]-mean)*rstd*lg4[q].z + lb4[q].z;
                    o4.w = (hval[q*4+3]-mean)*rstd*lg4[q].w + lb4[q].w;
                    *(float4*)(dst + q*4) = o4;
                }
            }
        }
    }
}

// ---------------- kernel 2: register-tiled projection + row l2norm ---------
__global__ void __launch_bounds__(256) proj2_kernel(
    const float* __restrict__ W, const int* __restrict__ gatherIdx,
    int nrows, int which)
{
    extern __shared__ float ps[];
    float* sW  = ps;              // [128][132] k-major W^T
    float* sAT = ps + 128*132;    // [128][68]  k-major A tile
    float* out = which ? g_q : g_Hk;

    const int tid = threadIdx.x;
    const int tx  = tid & 15, ty = tid >> 4;
    const int r0  = blockIdx.x*64;

    for (int idx=tid; idx<128*32; idx+=256){
        int j = idx >> 5, kq = idx & 31;
        float4 v = *(const float4*)&W[j*128 + kq*4];
        sW[(kq*4+0)*132 + j] = v.x;
        sW[(kq*4+1)*132 + j] = v.y;
        sW[(kq*4+2)*132 + j] = v.z;
        sW[(kq*4+3)*132 + j] = v.w;
    }
    for (int idx=tid; idx<64*32; idx+=256){
        int r = idx >> 5, kq = idx & 31;
        int gr = r0 + r;
        float4 v = make_float4(0.f,0.f,0.f,0.f);
        if (gr < nrows){
            int src = gatherIdx ? (gatherIdx[gr]*10 + 9) : gr;
            v = *(const float4*)&g_Hln[src*128 + kq*4];
        }
        sAT[(kq*4+0)*68 + r] = v.x;
        sAT[(kq*4+1)*68 + r] = v.y;
        sAT[(kq*4+2)*68 + r] = v.z;
        sAT[(kq*4+3)*68 + r] = v.w;
    }
    __syncthreads();

    u64 acc2[2][8];
    #pragma unroll
    for (int c=0;c<8;c++){ acc2[0][c]=0ull; acc2[1][c]=0ull; }

    const float* arow = &sAT[ty*4];
    const float* wrow = &sW[tx*8];
    #pragma unroll 4
    for (int k=0;k<128;k++){
        u64 alo, ahi;
        lds2u64(alo, ahi, &arow[k*68]);
        float4 w0 = *(const float4*)&wrow[k*132];
        float4 w1 = *(const float4*)&wrow[k*132 + 4];
        const float wv[8] = {w0.x,w0.y,w0.z,w0.w,w1.x,w1.y,w1.z,w1.w};
        #pragma unroll
        for (int c=0;c<8;c++){
            u64 bd = dup2(wv[c]);
            fma2(acc2[0][c], alo, bd);
            fma2(acc2[1][c], ahi, bd);
        }
    }

    float accf[4][8];
    #pragma unroll
    for (int c=0;c<8;c++){
        float2 lo = upk2(acc2[0][c]); accf[0][c]=lo.x; accf[1][c]=lo.y;
        float2 hi = upk2(acc2[1][c]); accf[2][c]=hi.x; accf[3][c]=hi.y;
    }
    #pragma unroll
    for (int r=0;r<4;r++){
        float ss=0.f;
        #pragma unroll
        for (int c=0;c<8;c++) ss += accf[r][c]*accf[r][c];
        #pragma unroll
        for (int o=8;o>=1;o>>=1) ss += __shfl_xor_sync(0xffffffffu, ss, o);
        float inv = 1.f/fmaxf(sqrtf(ss), 1e-12f);
        int gr = r0 + ty*4 + r;
        if (gr < nrows){
            float4 o0, o1;
            o0.x=accf[r][0]*inv; o0.y=accf[r][1]*inv; o0.z=accf[r][2]*inv; o0.w=accf[r][3]*inv;
            o1.x=accf[r][4]*inv; o1.y=accf[r][5]*inv; o1.z=accf[r][6]*inv; o1.w=accf[r][7]*inv;
            *(float4*)&out[gr*128 + tx*8]     = o0;
            *(float4*)&out[gr*128 + tx*8 + 4] = o1;
        }
    }
}

// ---------------- kernel 3: attention GEMM + fused top-5, cp.async 2-stage --
__global__ void __launch_bounds__(256) attn2_kernel(
    const float* __restrict__ log_temp, const float* __restrict__ lag_bias,
    const int*   __restrict__ target_idx)
{
    extern __shared__ float smem[];
    float* sAT = smem;                   // [128][68]  k-major A
    float* sB0 = smem + 128*68;          // [64][128]  swizzled B buf 0
    float* sB1 = sB0 + 64*128;           // [64][128]  swizzled B buf 1
    __shared__ float slb[10];
    __shared__ float sinvt;

    const int tid = threadIdx.x;
    const int tx  = tid & 15, ty = tid >> 4;
    const int rbase = blockIdx.x*64;

    if (tid < 10) slb[tid] = lag_bias[tid];
    if (tid == 0){
        float tp = __expf(log_temp[0]);
        tp = fminf(fmaxf(tp, 0.1f), 11.313708498984761f);
        sinvt = 1.f/tp;
    }

    for (int idx = tid; idx < 64*32; idx += 256){
        int row = idx >> 5, kq = idx & 31;
        int gr = rbase + row;
        float4 v = make_float4(0.f,0.f,0.f,0.f);
        if (gr < S_) v = *(const float4*)&g_q[gr*128 + kq*4];
        sAT[(kq*4+0)*68 + row] = v.x;
        sAT[(kq*4+1)*68 + row] = v.y;
        sAT[(kq*4+2)*68 + row] = v.z;
        sAT[(kq*4+3)*68 + row] = v.w;
    }

    int myst[4];
    #pragma unroll
    for (int i=0;i<4;i++){
        int gr = rbase + ty*4 + i;
        myst[i] = (gr < S_) ? target_idx[gr] : -1;
    }

    float tv[4][5]; int ti[4][5];
    #pragma unroll
    for (int r=0;r<4;r++)
        #pragma unroll
        for (int p=0;p<5;p++){ tv[r][p] = -FLT_MAX; ti[r][p] = 0x7fffffff; }

    const int tstart = blockIdx.y*TILES_PER_SPLIT_;
    const int tend   = min(tstart+TILES_PER_SPLIT_, NTILE_);
    const int nt     = tend - tstart;
    const int swz    = tx & 7;

    // async B tile loader
    auto load_tile = [&](float* sB, int tile){
        const int c0 = tile*64;
        for (int idx = tid; idx < 64*32; idx += 256){
            int col = idx >> 5, kq = idx & 31;
            int gc = c0 + col;
            bool v = (gc < SL_);
            const float* src = &g_Hk[(v ? gc : 0)*128 + kq*4];
            int ks = kq ^ ((col>>2)&7);
            cp16(&sB[col*128 + ks*4], src, v);
        }
        cp_commit();
    };

    load_tile(sB0, tstart);
    if (nt > 1) load_tile(sB1, tstart+1);

    for (int i = 0; i < nt; i++){
        float* cur = (i & 1) ? sB1 : sB0;
        const int c0 = (tstart + i)*64;
        if (i+1 < nt) asm volatile("cp.async.wait_group 1;" ::: "memory");
        else          asm volatile("cp.async.wait_group 0;" ::: "memory");
        __syncthreads();

        u64 acc2[2][4];
        #pragma unroll
        for (int c=0;c<4;c++){ acc2[0][c]=0ull; acc2[1][c]=0ull; }

        const float* arow  = &sAT[ty*4];
        const float* bbase = &cur[(tx*4)*128];

        #pragma unroll 4
        for (int kb = 0; kb < 32; kb++){
            u64 alo[4], ahi[4];
            #pragma unroll
            for (int kk=0;kk<4;kk++)
                lds2u64(alo[kk], ahi[kk], &arow[(kb*4+kk)*68]);
            const int ks = (kb ^ swz)*4;
            float4 Bf[4];
            Bf[0] = *(const float4*)&bbase[0*128 + ks];
            Bf[1] = *(const float4*)&bbase[1*128 + ks];
            Bf[2] = *(const float4*)&bbase[2*128 + ks];
            Bf[3] = *(const float4*)&bbase[3*128 + ks];
            const float* bv = (const float*)Bf;   // bv[c*4 + k]
            #pragma unroll
            for (int k=0;k<4;k++){
                #pragma unroll
                for (int c=0;c<4;c++){
                    u64 bd = dup2(bv[c*4+k]);
                    fma2(acc2[0][c], alo[k], bd);
                    fma2(acc2[1][c], ahi[k], bd);
                }
            }
        }

        float acc[4][4];
        #pragma unroll
        for (int c=0;c<4;c++){
            float2 lo = upk2(acc2[0][c]); acc[0][c]=lo.x; acc[1][c]=lo.y;
            float2 hi = upk2(acc2[1][c]); acc[2][c]=hi.x; acc[3][c]=hi.y;
        }

        const float invt = sinvt;
        #pragma unroll
        for (int c=0;c<4;c++){
            int gc = c0 + tx*4 + c;
            int s  = gc/10;
            int l  = gc - s*10;
            bool colok = (gc < SL_);
            float lb = slb[l];
            #pragma unroll
            for (int r=0;r<4;r++){
                if (!colok || s == myst[r]) continue;
                float sc = acc[r][c]*invt + lb;
                if (better(sc, gc, tv[r][4], ti[r][4])){
                    tv[r][4]=sc; ti[r][4]=gc;
                    #pragma unroll
                    for (int p=4;p>0;p--){
                        if (better(tv[r][p],ti[r][p],tv[r][p-1],ti[r][p-1])){
                            float tvv=tv[r][p]; tv[r][p]=tv[r][p-1]; tv[r][p-1]=tvv;
                            int   tii=ti[r][p]; ti[r][p]=ti[r][p-1]; ti[r][p-1]=tii;
                        }
                    }
                }
            }
        }
        __syncthreads();
        if (i+2 < nt) load_tile(cur, tstart+i+2);
    }

    // Merge 16 partial top-5 lists per row (alias smem)
    __syncthreads();
    float* mv = smem;                         // [64][16][5] floats (20KB)
    int*   mi = (int*)(smem + 64*16*5);       // [64][16][5] ints   (20KB)
    #pragma unroll
    for (int r=0;r<4;r++){
        int row = ty*4+r;
        #pragma unroll
        for (int p=0;p<5;p++){
            mv[(row*16+tx)*5+p] = tv[r][p];
            mi[(row*16+tx)*5+p] = ti[r][p];
        }
    }
    __syncthreads();
    if (tid < 64){
        int gr = rbase + tid;
        if (gr < S_){
            float* cv = &mv[tid*80];
            int*   ci = &mi[tid*80];
            for (int kk=0;kk<5;kk++){
                float bv=-FLT_MAX; int bi=0x7fffffff; int bp=0;
                for (int m=0;m<80;m++){
                    if (better(cv[m],ci[m],bv,bi)){ bv=cv[m]; bi=ci[m]; bp=m; }
                }
                g_pval[gr*40 + blockIdx.y*5 + kk]=bv;
                g_pidx[gr*40 + blockIdx.y*5 + kk]=bi;
                cv[bp]=-FLT_MAX; ci[bp]=0x7fffffff;
            }
        }
    }
}

// ---------------- kernel 4: merge + softmax + gather + MLP -----------------
__global__ void __launch_bounds__(256) final_kernel(
    const float* __restrict__ Xraw,
    const float* __restrict__ W1, const float* __restrict__ b1,
    const float* __restrict__ W2, const float* __restrict__ b2,
    const float* __restrict__ W3, const float* __restrict__ b3,
    float* __restrict__ out)
{
    int t = blockIdx.x*256 + threadIdx.x;
    if (t >= S_) return;
    float cv[NS5_]; int ci[NS5_];
    #pragma unroll
    for (int m=0;m<NS5_;m++){ cv[m]=g_pval[t*40+m]; ci[m]=g_pidx[t*40+m]; }
    float v5[5]; int i5[5];
    #pragma unroll
    for (int kk=0;kk<5;kk++){
        float bv=-FLT_MAX; int bi=0x7fffffff; int bp=0;
        #pragma unroll
        for (int m=0;m<NS5_;m++)
            if (better(cv[m],ci[m],bv,bi)){ bv=cv[m]; bi=ci[m]; bp=m; }
        v5[kk]=bv; i5[kk]=bi;
        cv[bp]=-FLT_MAX; ci[bp]=0x7fffffff;
    }
    float w[5]; float den=0.f;
    #pragma unroll
    for (int kk=0;kk<5;kk++){ w[kk]=__expf(v5[kk]-v5[0]); den+=w[kk]; }
    float invden = 1.f/den;
    float feat[12];
    float zagg[6] = {0,0,0,0,0,0};
    #pragma unroll
    for (int kk=0;kk<5;kk++){
        int idx = i5[kk];
        int leader = idx/10;
        int lag    = idx - leader*10;
        int pos    = 29 + lag;
        const float* zp = &Xraw[(leader*40 + pos)*6];
        float ww = w[kk]*invden;
        #pragma unroll
        for (int f=0;f<6;f++){
            float zf = zp[f];
            zagg[f] += ww*zf;
            if (kk==0) feat[6+f]=zf;
        }
    }
    #pragma unroll
    for (int f=0;f<6;f++) feat[f]=zagg[f];

    float h1[64];
    #pragma unroll
    for (int j=0;j<64;j++){
        float a = b1[j];
        #pragma unroll
        for (int f=0;f<12;f++) a += W1[j*12+f]*feat[f];
        h1[j] = fmaxf(a,0.f);
    }
    float h2[32];
    #pragma unroll
    for (int j=0;j<32;j++){
        float a = b2[j];
        #pragma unroll
        for (int f=0;f<64;f++) a += W2[j*64+f]*h1[f];
        h2[j] = fmaxf(a,0.f);
    }
    float a = b3[0];
    #pragma unroll
    for (int j=0;j<32;j++) a += W3[j]*h2[j];
    out[t] = a;
}

// ---------------- launch ----------------------------------------------------
extern "C" void kernel_launch(void* const* d_in, const int* in_sizes, int n_in,
                              void* d_out, int out_size)
{
    const float* Xs  =(const float*)d_in[0];
    const float* Xr  =(const float*)d_in[1];
    const int*   tgt =(const int*)  d_in[2];
    const float* Wih =(const float*)d_in[3];
    const float* Whh =(const float*)d_in[4];
    const float* bihp=(const float*)d_in[5];
    const float* bhhp=(const float*)d_in[6];
    const float* lng =(const float*)d_in[7];
    const float* lnb =(const float*)d_in[8];
    const float* WQ  =(const float*)d_in[9];
    const float* WK  =(const float*)d_in[10];
    const float* logt=(const float*)d_in[11];
    const float* lagb=(const float*)d_in[12];
    const float* W1  =(const float*)d_in[13];
    const float* b1  =(const float*)d_in[14];
    const float* W2  =(const float*)d_in[15];
    const float* b2  =(const float*)d_in[16];
    const float* W3  =(const float*)d_in[17];
    const float* b3  =(const float*)d_in[18];
    float* out = (float*)d_out;

    const int attn_smem = (128*68 + 2*64*128) * (int)sizeof(float);  // 100352 B
    const int proj_smem = (128*132 + 128*68) * (int)sizeof(float);   // 102400 B
    cudaFuncSetAttribute(attn2_kernel, cudaFuncAttributeMaxDynamicSharedMemorySize, attn_smem);
    cudaFuncSetAttribute(proj2_kernel, cudaFuncAttributeMaxDynamicSharedMemorySize, proj_smem);

    pack_whh<<<128,256>>>(Whh);
    lstm_kernel<<<NBLK_,256>>>(Xs, Wih, bihp, bhhp, lng, lnb);
    proj2_kernel<<<469,256, proj_smem>>>(WK, nullptr, SL_, 0);   // -> g_Hk
    proj2_kernel<<<47, 256, proj_smem>>>(WQ, tgt,     S_,  1);   // -> g_q
    attn2_kernel<<<dim3(47,NSPLIT_),256, attn_smem>>>(logt, lagb, tgt);
    final_kernel<<<12,256>>>(Xr, W1,b1, W2,b2, W3,b3, out);
}

// round 7
// speedup vs baseline: 1.3443x; 1.3443x over previous
#include <cuda_runtime.h>
#include <math.h>
#include <float.h>

#define S_    3000
#define F_    6
#define N_    128
#define L_    40
#define LMAX_ 10
#define K_    5
#define SL_   (S_*LMAX_)   // 30000
#define NSPLIT_ 6
#define NS5_  (NSPLIT_*K_) // 30
#define ANTILE_ 235        // ceil(30000/128)
#define ART_  128          // attn rows per block
#define NBLK_ 250          // LSTM blocks (12 stocks each)

typedef unsigned long long u64;

// ---------------- f32x2 packed-FMA helpers (sm_100+) ------------------------
__device__ __forceinline__ u64 pk2(float lo, float hi){
    u64 r;
    asm("mov.b64 %0,{%1,%2};" : "=l"(r)
        : "r"(__float_as_uint(lo)), "r"(__float_as_uint(hi)));
    return r;
}
__device__ __forceinline__ u64 dup2(float v){ return pk2(v, v); }
__device__ __forceinline__ float2 upk2(u64 v){
    unsigned lo, hi;
    asm("mov.b64 {%0,%1},%2;" : "=r"(lo), "=r"(hi) : "l"(v));
    float2 f; f.x = __uint_as_float(lo); f.y = __uint_as_float(hi); return f;
}
__device__ __forceinline__ void fma2(u64& d, u64 a, u64 b){
    asm("fma.rn.f32x2 %0,%1,%2,%0;" : "+l"(d) : "l"(a), "l"(b));
}

// ---------------- cp.async helpers ------------------------------------------
__device__ __forceinline__ void cp16(float* dst, const float* src, bool valid){
    unsigned d = (unsigned)__cvta_generic_to_shared(dst);
    int sz = valid ? 16 : 0;
    asm volatile("cp.async.cg.shared.global [%0], [%1], 16, %2;"
                 :: "r"(d), "l"(src), "r"(sz));
}
__device__ __forceinline__ void cp_commit(){
    asm volatile("cp.async.commit_group;" ::: "memory");
}

// ---------------- scratch (device globals; no allocations allowed) ----------
__device__ u64   g_Whh2[128*256];        // [k][256] u64 = packed col-pairs of Whh^T
__device__ float g_Hln[SL_*N_];          // [30000][128] layernormed H, t in [30,40)
__device__ float g_Hk [SL_*N_];          // l2norm(Hln @ WK^T)
__device__ float g_q  [S_*N_];           // l2norm(Hln[tgt,9] @ WQ^T)
__device__ float g_pval[S_*40];          // 6 splits x top5 per target
__device__ int   g_pidx[S_*40];

__device__ __forceinline__ float sigf(float x){ return 1.f/(1.f+__expf(-x)); }
__device__ __forceinline__ float tanhfast(float x){ return 2.f/(1.f+__expf(-2.f*x)) - 1.f; }
__device__ __forceinline__ bool better(float v,int i,float bv,int bi){
    return (v>bv) || (v==bv && i<bi);
}

// ---------------- kernel 0: pack Whh -> g_Whh2 [k][j] = (Whh[2j][k],Whh[2j+1][k])
__global__ void __launch_bounds__(256) pack_whh(const float* __restrict__ Whh){
    int idx = blockIdx.x*256 + threadIdx.x;          // 32768 elements
    if (idx < 128*256){
        int k = idx >> 8, j = idx & 255;
        g_Whh2[idx] = pk2(Whh[(2*j)*128 + k], Whh[(2*j+1)*128 + k]);
    }
}

// ---------------- kernel 1: LSTM (12 stocks/block, proven 1419us version) ---
__global__ void __launch_bounds__(256,1) lstm_kernel(
    const float* __restrict__ X,   const float* __restrict__ Wih,
    const float* __restrict__ bih, const float* __restrict__ bhh,
    const float* __restrict__ lng, const float* __restrict__ lnb)
{
    __shared__ float shT[128*14];        // h transposed: [k][stock], pad 14
    __shared__ float sg[12][516];        // gates [stock][512+pad]
    __shared__ u64   sx2[240*6];         // x packed stock-pairs: [t*6+f][pair]
    const int tid = threadIdx.x;
    const int bs0 = blockIdx.x*12;

    for (int idx = tid; idx < 240*6; idx += 256){
        int tf = idx/6, p = idx - (idx/6)*6;
        sx2[tf*6 + p] = pk2(X[(bs0 + 2*p)*240 + tf], X[(bs0 + 2*p+1)*240 + tf]);
    }
    for (int idx = tid; idx < 128*14; idx += 256) shT[idx] = 0.f;

    const int j0 = tid*2;
    u64 wih_d[2][6];
    #pragma unroll
    for (int c=0;c<2;c++)
        #pragma unroll
        for (int f=0;f<6;f++) wih_d[c][f] = dup2(Wih[(j0+c)*6 + f]);
    u64 bias_d[2];
    bias_d[0] = dup2(bih[j0]   + bhh[j0]);
    bias_d[1] = dup2(bih[j0+1] + bhh[j0+1]);

    const int su = tid >> 4;             // 0..15 (active if <12)
    const int n0 = (tid & 15)*8;         // unit base, 8 units
    float4 cA = make_float4(0.f,0.f,0.f,0.f);
    float4 cB = make_float4(0.f,0.f,0.f,0.f);
    float4 gA4, gB4, bA4, bB4;
    if (su < 12){
        gA4 = *(const float4*)&lng[n0];   gB4 = *(const float4*)&lng[n0+4];
        bA4 = *(const float4*)&lnb[n0];   bB4 = *(const float4*)&lnb[n0+4];
    }

    for (int t=0; t<40; t++){
        __syncthreads();
        u64 acc[6][2];
        #pragma unroll
        for (int p=0;p<6;p++){ acc[p][0]=bias_d[0]; acc[p][1]=bias_d[1]; }
        #pragma unroll
        for (int f=0;f<6;f++){
            u64 w0 = wih_d[0][f], w1 = wih_d[1][f];
            #pragma unroll
            for (int p=0;p<6;p++){
                u64 xp = sx2[(t*6+f)*6 + p];
                fma2(acc[p][0], xp, w0);
                fma2(acc[p][1], xp, w1);
            }
        }
        #pragma unroll 2
        for (int k4=0; k4<32; k4++){
            u64 w2[4];
            #pragma unroll
            for (int kk=0;kk<4;kk++)
                w2[kk] = g_Whh2[(k4*4+kk)*256 + tid];
            #pragma unroll
            for (int kk=0;kk<4;kk++){
                int k = k4*4+kk;
                float2 wf = upk2(w2[kk]);
                u64 wd0 = dup2(wf.x), wd1 = dup2(wf.y);
                #pragma unroll
                for (int p=0;p<6;p++){
                    u64 hp = *(const u64*)&shT[k*14 + 2*p];
                    fma2(acc[p][0], hp, wd0);
                    fma2(acc[p][1], hp, wd1);
                }
            }
        }
        #pragma unroll
        for (int p=0;p<6;p++){
            float2 a0 = upk2(acc[p][0]);
            float2 a1 = upk2(acc[p][1]);
            sg[2*p  ][j0  ] = a0.x;
            sg[2*p+1][j0  ] = a0.y;
            sg[2*p  ][j0+1] = a1.x;
            sg[2*p+1][j0+1] = a1.y;
        }
        __syncthreads();

        if (su < 12){
            float4 giA = *(const float4*)&sg[su][n0];
            float4 giB = *(const float4*)&sg[su][n0+4];
            float4 gfA = *(const float4*)&sg[su][128+n0];
            float4 gfB = *(const float4*)&sg[su][128+n0+4];
            float4 ggA = *(const float4*)&sg[su][256+n0];
            float4 ggB = *(const float4*)&sg[su][256+n0+4];
            float4 goA = *(const float4*)&sg[su][384+n0];
            float4 goB = *(const float4*)&sg[su][384+n0+4];

            cA.x = sigf(gfA.x)*cA.x + sigf(giA.x)*tanhfast(ggA.x);
            cA.y = sigf(gfA.y)*cA.y + sigf(giA.y)*tanhfast(ggA.y);
            cA.z = sigf(gfA.z)*cA.z + sigf(giA.z)*tanhfast(ggA.z);
            cA.w = sigf(gfA.w)*cA.w + sigf(giA.w)*tanhfast(ggA.w);
            cB.x = sigf(gfB.x)*cB.x + sigf(giB.x)*tanhfast(ggB.x);
            cB.y = sigf(gfB.y)*cB.y + sigf(giB.y)*tanhfast(ggB.y);
            cB.z = sigf(gfB.z)*cB.z + sigf(giB.z)*tanhfast(ggB.z);
            cB.w = sigf(gfB.w)*cB.w + sigf(giB.w)*tanhfast(ggB.w);

            float hA0 = sigf(goA.x)*tanhfast(cA.x);
            float hA1 = sigf(goA.y)*tanhfast(cA.y);
            float hA2 = sigf(goA.z)*tanhfast(cA.z);
            float hA3 = sigf(goA.w)*tanhfast(cA.w);
            float hB0 = sigf(goB.x)*tanhfast(cB.x);
            float hB1 = sigf(goB.y)*tanhfast(cB.y);
            float hB2 = sigf(goB.z)*tanhfast(cB.z);
            float hB3 = sigf(goB.w)*tanhfast(cB.w);

            shT[(n0+0)*14 + su] = hA0;
            shT[(n0+1)*14 + su] = hA1;
            shT[(n0+2)*14 + su] = hA2;
            shT[(n0+3)*14 + su] = hA3;
            shT[(n0+4)*14 + su] = hB0;
            shT[(n0+5)*14 + su] = hB1;
            shT[(n0+6)*14 + su] = hB2;
            shT[(n0+7)*14 + su] = hB3;

            if (t >= 30){
                float sum = hA0+hA1+hA2+hA3+hB0+hB1+hB2+hB3;
                float ssq = hA0*hA0+hA1*hA1+hA2*hA2+hA3*hA3
                          + hB0*hB0+hB1*hB1+hB2*hB2+hB3*hB3;
                #pragma unroll
                for (int o=8;o>=1;o>>=1){
                    sum += __shfl_xor_sync(0xffffffffu, sum, o, 16);
                    ssq += __shfl_xor_sync(0xffffffffu, ssq, o, 16);
                }
                float mean = sum*(1.f/128.f);
                float var  = ssq*(1.f/128.f) - mean*mean;
                float rstd = rsqrtf(var + 1e-5f);
                float4 oA, oB;
                oA.x = (hA0-mean)*rstd*gA4.x + bA4.x;
                oA.y = (hA1-mean)*rstd*gA4.y + bA4.y;
                oA.z = (hA2-mean)*rstd*gA4.z + bA4.z;
                oA.w = (hA3-mean)*rstd*gA4.w + bA4.w;
                oB.x = (hB0-mean)*rstd*gB4.x + bB4.x;
                oB.y = (hB1-mean)*rstd*gB4.y + bB4.y;
                oB.z = (hB2-mean)*rstd*gB4.z + bB4.z;
                oB.w = (hB3-mean)*rstd*gB4.w + bB4.w;
                float* dst = &g_Hln[((bs0+su)*10 + (t-30))*128 + n0];
                *(float4*)dst       = oA;
                *(float4*)(dst + 4) = oB;
            }
        }
    }
}

// ---------------- kernel 2: register-tiled projection + row l2norm ---------
__global__ void __launch_bounds__(256) proj2_kernel(
    const float* __restrict__ W, const int* __restrict__ gatherIdx,
    int nrows, int which)
{
    extern __shared__ float ps[];
    float* sW  = ps;              // [128][132] k-major W^T
    float* sAT = ps + 128*132;    // [128][68]  k-major A tile
    float* out = which ? g_q : g_Hk;

    const int tid = threadIdx.x;
    const int tx  = tid & 15, ty = tid >> 4;
    const int r0  = blockIdx.x*64;

    for (int idx=tid; idx<128*32; idx+=256){
        int j = idx >> 5, kq = idx & 31;
        float4 v = *(const float4*)&W[j*128 + kq*4];
        sW[(kq*4+0)*132 + j] = v.x;
        sW[(kq*4+1)*132 + j] = v.y;
        sW[(kq*4+2)*132 + j] = v.z;
        sW[(kq*4+3)*132 + j] = v.w;
    }
    for (int idx=tid; idx<64*32; idx+=256){
        int r = idx >> 5, kq = idx & 31;
        int gr = r0 + r;
        float4 v = make_float4(0.f,0.f,0.f,0.f);
        if (gr < nrows){
            int src = gatherIdx ? (gatherIdx[gr]*10 + 9) : gr;
            v = *(const float4*)&g_Hln[src*128 + kq*4];
        }
        sAT[(kq*4+0)*68 + r] = v.x;
        sAT[(kq*4+1)*68 + r] = v.y;
        sAT[(kq*4+2)*68 + r] = v.z;
        sAT[(kq*4+3)*68 + r] = v.w;
    }
    __syncthreads();

    u64 acc2[2][8];
    #pragma unroll
    for (int c=0;c<8;c++){ acc2[0][c]=0ull; acc2[1][c]=0ull; }

    const float* arow = &sAT[ty*4];
    const float* wrow = &sW[tx*8];
    #pragma unroll 4
    for (int k=0;k<128;k++){
        float4 av = *(const float4*)&arow[k*68];
        float4 w0 = *(const float4*)&wrow[k*132];
        float4 w1 = *(const float4*)&wrow[k*132 + 4];
        u64 alo = pk2(av.x, av.y);
        u64 ahi = pk2(av.z, av.w);
        const float wv[8] = {w0.x,w0.y,w0.z,w0.w,w1.x,w1.y,w1.z,w1.w};
        #pragma unroll
        for (int c=0;c<8;c++){
            u64 bd = dup2(wv[c]);
            fma2(acc2[0][c], alo, bd);
            fma2(acc2[1][c], ahi, bd);
        }
    }

    float accf[4][8];
    #pragma unroll
    for (int c=0;c<8;c++){
        float2 lo = upk2(acc2[0][c]); accf[0][c]=lo.x; accf[1][c]=lo.y;
        float2 hi = upk2(acc2[1][c]); accf[2][c]=hi.x; accf[3][c]=hi.y;
    }
    #pragma unroll
    for (int r=0;r<4;r++){
        float ss=0.f;
        #pragma unroll
        for (int c=0;c<8;c++) ss += accf[r][c]*accf[r][c];
        #pragma unroll
        for (int o=8;o>=1;o>>=1) ss += __shfl_xor_sync(0xffffffffu, ss, o);
        float inv = 1.f/fmaxf(sqrtf(ss), 1e-12f);
        int gr = r0 + ty*4 + r;
        if (gr < nrows){
            float4 o0, o1;
            o0.x=accf[r][0]*inv; o0.y=accf[r][1]*inv; o0.z=accf[r][2]*inv; o0.w=accf[r][3]*inv;
            o1.x=accf[r][4]*inv; o1.y=accf[r][5]*inv; o1.z=accf[r][6]*inv; o1.w=accf[r][7]*inv;
            *(float4*)&out[gr*128 + tx*8]     = o0;
            *(float4*)&out[gr*128 + tx*8 + 4] = o1;
        }
    }
}

// ---------------- kernel 3: 128x128-tile attention GEMM + fused top-5 ------
// 256 threads, 8x8 micro-tile, cp.async double buffer, 1 block/SM.
// grid (24 row tiles, 6 interleaved col splits). smem 198656 B.
__global__ void __launch_bounds__(256,1) attn3_kernel(
    const float* __restrict__ log_temp, const float* __restrict__ lag_bias,
    const int*   __restrict__ target_idx)
{
    extern __shared__ float smem[];
    float* sA  = smem;                   // [128k][132] k-major A (q)
    float* sB0 = smem + 128*132;         // [128c][128k] swizzled B buf 0
    float* sB1 = sB0 + 128*128;          // buf 1
    __shared__ float slb[10];
    __shared__ float sinvt;

    const int tid = threadIdx.x;
    const int tx  = tid & 15, ty = tid >> 4;
    const int rbase = blockIdx.x*ART_;

    if (tid < 10) slb[tid] = lag_bias[tid];
    if (tid == 0){
        float tp = __expf(log_temp[0]);
        tp = fminf(fmaxf(tp, 0.1f), 11.313708498984761f);
        sinvt = 1.f/tp;
    }

    // Load A tile (128 rows x 128 k), store k-major, pad 132
    for (int idx = tid; idx < 128*32; idx += 256){
        int row = idx >> 5, kq = idx & 31;
        int gr = rbase + row;
        float4 v = make_float4(0.f,0.f,0.f,0.f);
        if (gr < S_) v = *(const float4*)&g_q[gr*128 + kq*4];
        sA[(kq*4+0)*132 + row] = v.x;
        sA[(kq*4+1)*132 + row] = v.y;
        sA[(kq*4+2)*132 + row] = v.z;
        sA[(kq*4+3)*132 + row] = v.w;
    }

    int myst[8];
    #pragma unroll
    for (int i=0;i<8;i++){
        int gr = rbase + ty*8 + i;
        myst[i] = (gr < S_) ? target_idx[gr] : -1;
    }

    float tv[8][5]; int ti[8][5];
    #pragma unroll
    for (int r=0;r<8;r++)
        #pragma unroll
        for (int p=0;p<5;p++){ tv[r][p] = -FLT_MAX; ti[r][p] = 0x7fffffff; }

    const int y  = blockIdx.y;
    const int nt = (ANTILE_ - y + NSPLIT_ - 1)/NSPLIT_;   // 39 or 40
    const int swz = tx & 7;

    // async B tile loader; tile j of this split covers cols (y + 6j)*128 ..
    auto load_tile = [&](float* sB, int j){
        const int c0 = (y + NSPLIT_*j)*128;
        for (int idx = tid; idx < 128*32; idx += 256){
            int col = idx >> 5, kq = idx & 31;
            int gc = c0 + col;
            bool v = (gc < SL_);
            const float* src = &g_Hk[(v ? gc : 0)*128 + kq*4];
            int ks = kq ^ ((col>>3)&7);
            cp16(&sB[col*128 + ks*4], src, v);
        }
        cp_commit();
    };

    load_tile(sB0, 0);
    if (nt > 1) load_tile(sB1, 1);

    for (int i = 0; i < nt; i++){
        float* cur = (i & 1) ? sB1 : sB0;
        const int c0 = (y + NSPLIT_*i)*128;
        if (i+1 < nt) asm volatile("cp.async.wait_group 1;" ::: "memory");
        else          asm volatile("cp.async.wait_group 0;" ::: "memory");
        __syncthreads();

        u64 acc2[4][8];
        #pragma unroll
        for (int rr=0;rr<4;rr++)
            #pragma unroll
            for (int c=0;c<8;c++) acc2[rr][c]=0ull;

        const float* arow = &sA[ty*8];

        #pragma unroll 2
        for (int kb = 0; kb < 32; kb++){
            const int ks = (kb ^ swz)*4;
            float4 Bf[8];
            #pragma unroll
            for (int c=0;c<8;c++)
                Bf[c] = *(const float4*)&cur[(tx*8+c)*128 + ks];
            #pragma unroll
            for (int kk=0;kk<4;kk++){
                ulonglong2 a01 = *(const ulonglong2*)&arow[(kb*4+kk)*132];
                ulonglong2 a23 = *(const ulonglong2*)&arow[(kb*4+kk)*132 + 4];
                #pragma unroll
                for (int c=0;c<8;c++){
                    u64 bd = dup2(((const float*)&Bf[c])[kk]);
                    fma2(acc2[0][c], a01.x, bd);
                    fma2(acc2[1][c], a01.y, bd);
                    fma2(acc2[2][c], a23.x, bd);
                    fma2(acc2[3][c], a23.y, bd);
                }
            }
        }

        // epilogue: scores + top-5 update (registers)
        const float invt = sinvt;
        #pragma unroll
        for (int c=0;c<8;c++){
            int gc = c0 + tx*8 + c;
            int s  = gc/10;
            int l  = gc - s*10;
            bool colok = (gc < SL_);
            float lb = slb[l];
            float2 p0 = upk2(acc2[0][c]);
            float2 p1 = upk2(acc2[1][c]);
            float2 p2 = upk2(acc2[2][c]);
            float2 p3 = upk2(acc2[3][c]);
            float sc[8] = {p0.x,p0.y,p1.x,p1.y,p2.x,p2.y,p3.x,p3.y};
            #pragma unroll
            for (int r=0;r<8;r++){
                if (!colok || s == myst[r]) continue;
                float v = sc[r]*invt + lb;
                if (better(v, gc, tv[r][4], ti[r][4])){
                    tv[r][4]=v; ti[r][4]=gc;
                    #pragma unroll
                    for (int p=4;p>0;p--){
                        if (better(tv[r][p],ti[r][p],tv[r][p-1],ti[r][p-1])){
                            float tvv=tv[r][p]; tv[r][p]=tv[r][p-1]; tv[r][p-1]=tvv;
                            int   tii=ti[r][p]; ti[r][p]=ti[r][p-1]; ti[r][p-1]=tii;
                        }
                    }
                }
            }
        }
        __syncthreads();
        if (i+2 < nt) load_tile(cur, i+2);
    }

    // Merge 16 partial top-5 lists per row (alias smem over tiles)
    __syncthreads();
    float* mv = smem;                         // [128][16][5] floats (40KB)
    int*   mi = (int*)(smem + 128*16*5);      // [128][16][5] ints   (40KB)
    #pragma unroll
    for (int r=0;r<8;r++){
        int row = ty*8+r;
        #pragma unroll
        for (int p=0;p<5;p++){
            mv[(row*16+tx)*5+p] = tv[r][p];
            mi[(row*16+tx)*5+p] = ti[r][p];
        }
    }
    __syncthreads();
    if (tid < 128){
        int gr = rbase + tid;
        if (gr < S_){
            float* cv = &mv[tid*80];
            int*   ci = &mi[tid*80];
            for (int kk=0;kk<5;kk++){
                float bv=-FLT_MAX; int bi=0x7fffffff; int bp=0;
                for (int m=0;m<80;m++){
                    if (better(cv[m],ci[m],bv,bi)){ bv=cv[m]; bi=ci[m]; bp=m; }
                }
                g_pval[gr*40 + y*5 + kk]=bv;
                g_pidx[gr*40 + y*5 + kk]=bi;
                cv[bp]=-FLT_MAX; ci[bp]=0x7fffffff;
            }
        }
    }
}

// ---------------- kernel 4: merge + softmax + gather + MLP -----------------
__global__ void __launch_bounds__(256) final_kernel(
    const float* __restrict__ Xraw,
    const float* __restrict__ W1, const float* __restrict__ b1,
    const float* __restrict__ W2, const float* __restrict__ b2,
    const float* __restrict__ W3, const float* __restrict__ b3,
    float* __restrict__ out)
{
    int t = blockIdx.x*256 + threadIdx.x;
    if (t >= S_) return;
    float cv[NS5_]; int ci[NS5_];
    #pragma unroll
    for (int m=0;m<NS5_;m++){ cv[m]=g_pval[t*40+m]; ci[m]=g_pidx[t*40+m]; }
    float v5[5]; int i5[5];
    #pragma unroll
    for (int kk=0;kk<5;kk++){
        float bv=-FLT_MAX; int bi=0x7fffffff; int bp=0;
        #pragma unroll
        for (int m=0;m<NS5_;m++)
            if (better(cv[m],ci[m],bv,bi)){ bv=cv[m]; bi=ci[m]; bp=m; }
        v5[kk]=bv; i5[kk]=bi;
        cv[bp]=-FLT_MAX; ci[bp]=0x7fffffff;
    }
    float w[5]; float den=0.f;
    #pragma unroll
    for (int kk=0;kk<5;kk++){ w[kk]=__expf(v5[kk]-v5[0]); den+=w[kk]; }
    float invden = 1.f/den;
    float feat[12];
    float zagg[6] = {0,0,0,0,0,0};
    #pragma unroll
    for (int kk=0;kk<5;kk++){
        int idx = i5[kk];
        int leader = idx/10;
        int lag    = idx - leader*10;
        int pos    = 29 + lag;
        const float* zp = &Xraw[(leader*40 + pos)*6];
        float ww = w[kk]*invden;
        #pragma unroll
        for (int f=0;f<6;f++){
            float zf = zp[f];
            zagg[f] += ww*zf;
            if (kk==0) feat[6+f]=zf;
        }
    }
    #pragma unroll
    for (int f=0;f<6;f++) feat[f]=zagg[f];

    float h1[64];
    #pragma unroll
    for (int j=0;j<64;j++){
        float a = b1[j];
        #pragma unroll
        for (int f=0;f<12;f++) a += W1[j*12+f]*feat[f];
        h1[j] = fmaxf(a,0.f);
    }
    float h2[32];
    #pragma unroll
    for (int j=0;j<32;j++){
        float a = b2[j];
        #pragma unroll
        for (int f=0;f<64;f++) a += W2[j*64+f]*h1[f];
        h2[j] = fmaxf(a,0.f);
    }
    float a = b3[0];
    #pragma unroll
    for (int j=0;j<32;j++) a += W3[j]*h2[j];
    out[t] = a;
}

// ---------------- launch ----------------------------------------------------
extern "C" void kernel_launch(void* const* d_in, const int* in_sizes, int n_in,
                              void* d_out, int out_size)
{
    const float* Xs  =(const float*)d_in[0];
    const float* Xr  =(const float*)d_in[1];
    const int*   tgt =(const int*)  d_in[2];
    const float* Wih =(const float*)d_in[3];
    const float* Whh =(const float*)d_in[4];
    const float* bihp=(const float*)d_in[5];
    const float* bhhp=(const float*)d_in[6];
    const float* lng =(const float*)d_in[7];
    const float* lnb =(const float*)d_in[8];
    const float* WQ  =(const float*)d_in[9];
    const float* WK  =(const float*)d_in[10];
    const float* logt=(const float*)d_in[11];
    const float* lagb=(const float*)d_in[12];
    const float* W1  =(const float*)d_in[13];
    const float* b1  =(const float*)d_in[14];
    const float* W2  =(const float*)d_in[15];
    const float* b2  =(const float*)d_in[16];
    const float* W3  =(const float*)d_in[17];
    const float* b3  =(const float*)d_in[18];
    float* out = (float*)d_out;

    const int attn_smem = (128*132 + 2*128*128) * (int)sizeof(float);  // 198656 B
    const int proj_smem = (128*132 + 128*68) * (int)sizeof(float);     // 102400 B
    cudaFuncSetAttribute(attn3_kernel, cudaFuncAttributeMaxDynamicSharedMemorySize, attn_smem);
    cudaFuncSetAttribute(proj2_kernel, cudaFuncAttributeMaxDynamicSharedMemorySize, proj_smem);

    pack_whh<<<128,256>>>(Whh);
    lstm_kernel<<<NBLK_,256>>>(Xs, Wih, bihp, bhhp, lng, lnb);
    proj2_kernel<<<469,256, proj_smem>>>(WK, nullptr, SL_, 0);   // -> g_Hk
    proj2_kernel<<<47, 256, proj_smem>>>(WQ, tgt,     S_,  1);   // -> g_q
    attn3_kernel<<<dim3(24,NSPLIT_),256, attn_smem>>>(logt, lagb, tgt);
    final_kernel<<<12,256>>>(Xr, W1,b1, W2,b2, W3,b3, out);
}

// round 12
// speedup vs baseline: 1.5907x; 1.1833x over previous
#include <cuda_runtime.h>
#include <cuda_pipeline.h>
#include <math.h>
#include <float.h>

#define S_    3000
#define F_    6
#define N_    128
#define L_    40
#define LMAX_ 10
#define K_    5
#define SL_   (S_*LMAX_)   // 30000
#define NTILE_ 469         // ceil(30000/64)
#define NSPLIT_ 6
#define TILES_PER_SPLIT_ 79
#define NS5_  (NSPLIT_*K_) // 30
#define NBLK_ 250          // LSTM blocks (12 stocks each)

// ---------------- scratch (device globals; no allocations allowed) ----------
__device__ float2 g_Whh2f[128*256];      // [k][j] = (Whh[2j][k], Whh[2j+1][k])
__device__ float  g_Hln[SL_*N_];         // [30000][128] layernormed H, t in [30,40)
__device__ float  g_Hk [SL_*N_];         // l2norm(Hln @ WK^T)
__device__ float  g_q  [S_*N_];          // l2norm(Hln[tgt,9] @ WQ^T)
__device__ float  g_pval[S_*40];         // 6 splits x top5 per target
__device__ int    g_pidx[S_*40];

__device__ __forceinline__ float sigf(float x){ return 1.f/(1.f+__expf(-x)); }
__device__ __forceinline__ float tanhfast(float x){ return 2.f/(1.f+__expf(-2.f*x)) - 1.f; }
__device__ __forceinline__ bool better(float v,int i,float bv,int bi){
    return (v>bv) || (v==bv && i<bi);
}

// ---------------- kernel 0: pack Whh -> g_Whh2f[k*256+j] --------------------
__global__ void __launch_bounds__(256) pack_whh(const float* __restrict__ Whh){
    int idx = blockIdx.x*256 + threadIdx.x;          // 32768 elements
    if (idx < 128*256){
        int k = idx >> 8, j = idx & 255;
        g_Whh2f[idx] = make_float2(Whh[(2*j)*128 + k], Whh[(2*j+1)*128 + k]);
    }
}

// ---------------- kernel 1: LSTM (+ fused LayerNorm for t>=30) --------------
// 12 stocks per block, 256 threads, 250 blocks. Plain fp32 math.
// GEMM phase: thread owns 2 gate cols (j0=2*tid) for ALL 12 stocks.
// Whh read ONCE per block per step. Update: su=tid>>4 (<12), 8 units.
__global__ void __launch_bounds__(256) lstm_kernel(
    const float* __restrict__ X,   const float* __restrict__ Wih,
    const float* __restrict__ bih, const float* __restrict__ bhh,
    const float* __restrict__ lng, const float* __restrict__ lnb)
{
    __shared__ float  shT[128*14];       // h transposed: [k][stock], pad 14
    __shared__ float  sg[12][516];       // gates [stock][512+pad]
    __shared__ float2 sx2[240*6];        // x stock-pairs: [t*6+f][pair]
    const int tid = threadIdx.x;
    const int bs0 = blockIdx.x*12;

    for (int idx = tid; idx < 240*6; idx += 256){
        int tf = idx/6, p = idx - (idx/6)*6;
        sx2[tf*6 + p] = make_float2(X[(bs0 + 2*p)*240 + tf],
                                    X[(bs0 + 2*p+1)*240 + tf]);
    }
    for (int idx = tid; idx < 128*14; idx += 256) shT[idx] = 0.f;

    const int j0 = tid*2;
    float wih0[6], wih1[6];
    #pragma unroll
    for (int f=0;f<6;f++){
        wih0[f] = Wih[(j0  )*6 + f];
        wih1[f] = Wih[(j0+1)*6 + f];
    }
    const float bb0 = bih[j0]   + bhh[j0];
    const float bb1 = bih[j0+1] + bhh[j0+1];

    const int su = tid >> 4;             // 0..15 (active if <12)
    const int n0 = (tid & 15)*8;         // unit base, 8 units
    float4 cA = make_float4(0.f,0.f,0.f,0.f);
    float4 cB = make_float4(0.f,0.f,0.f,0.f);
    float4 gA4, gB4, bA4, bB4;
    if (su < 12){
        gA4 = *(const float4*)&lng[n0];   gB4 = *(const float4*)&lng[n0+4];
        bA4 = *(const float4*)&lnb[n0];   bB4 = *(const float4*)&lnb[n0+4];
    }

    for (int t=0; t<40; t++){
        __syncthreads();
        // acc[p][colpair]: a0x/a0y = col j0 (even/odd stock), a1x/a1y = col j0+1
        float a0x[6], a0y[6], a1x[6], a1y[6];
        #pragma unroll
        for (int p=0;p<6;p++){ a0x[p]=bb0; a0y[p]=bb0; a1x[p]=bb1; a1y[p]=bb1; }
        #pragma unroll
        for (int f=0;f<6;f++){
            float w0 = wih0[f], w1 = wih1[f];
            #pragma unroll
            for (int p=0;p<6;p++){
                float2 xp = sx2[(t*6+f)*6 + p];
                a0x[p] += xp.x*w0; a0y[p] += xp.y*w0;
                a1x[p] += xp.x*w1; a1y[p] += xp.y*w1;
            }
        }
        #pragma unroll 4
        for (int k=0; k<128; k++){
            float2 wf = g_Whh2f[k*256 + tid];   // (Whh[j0][k], Whh[j0+1][k])
            #pragma unroll
            for (int p=0;p<6;p++){
                float2 hp = *(const float2*)&shT[k*14 + 2*p];
                a0x[p] += hp.x*wf.x; a0y[p] += hp.y*wf.x;
                a1x[p] += hp.x*wf.y; a1y[p] += hp.y*wf.y;
            }
        }
        #pragma unroll
        for (int p=0;p<6;p++){
            sg[2*p  ][j0  ] = a0x[p];
            sg[2*p+1][j0  ] = a0y[p];
            sg[2*p  ][j0+1] = a1x[p];
            sg[2*p+1][j0+1] = a1y[p];
        }
        __syncthreads();

        if (su < 12){
            float4 giA = *(const float4*)&sg[su][n0];
            float4 giB = *(const float4*)&sg[su][n0+4];
            float4 gfA = *(const float4*)&sg[su][128+n0];
            float4 gfB = *(const float4*)&sg[su][128+n0+4];
            float4 ggA = *(const float4*)&sg[su][256+n0];
            float4 ggB = *(const float4*)&sg[su][256+n0+4];
            float4 goA = *(const float4*)&sg[su][384+n0];
            float4 goB = *(const float4*)&sg[su][384+n0+4];

            cA.x = sigf(gfA.x)*cA.x + sigf(giA.x)*tanhfast(ggA.x);
            cA.y = sigf(gfA.y)*cA.y + sigf(giA.y)*tanhfast(ggA.y);
            cA.z = sigf(gfA.z)*cA.z + sigf(giA.z)*tanhfast(ggA.z);
            cA.w = sigf(gfA.w)*cA.w + sigf(giA.w)*tanhfast(ggA.w);
            cB.x = sigf(gfB.x)*cB.x + sigf(giB.x)*tanhfast(ggB.x);
            cB.y = sigf(gfB.y)*cB.y + sigf(giB.y)*tanhfast(ggB.y);
            cB.z = sigf(gfB.z)*cB.z + sigf(giB.z)*tanhfast(ggB.z);
            cB.w = sigf(gfB.w)*cB.w + sigf(giB.w)*tanhfast(ggB.w);

            float hA0 = sigf(goA.x)*tanhfast(cA.x);
            float hA1 = sigf(goA.y)*tanhfast(cA.y);
            float hA2 = sigf(goA.z)*tanhfast(cA.z);
            float hA3 = sigf(goA.w)*tanhfast(cA.w);
            float hB0 = sigf(goB.x)*tanhfast(cB.x);
            float hB1 = sigf(goB.y)*tanhfast(cB.y);
            float hB2 = sigf(goB.z)*tanhfast(cB.z);
            float hB3 = sigf(goB.w)*tanhfast(cB.w);

            shT[(n0+0)*14 + su] = hA0;
            shT[(n0+1)*14 + su] = hA1;
            shT[(n0+2)*14 + su] = hA2;
            shT[(n0+3)*14 + su] = hA3;
            shT[(n0+4)*14 + su] = hB0;
            shT[(n0+5)*14 + su] = hB1;
            shT[(n0+6)*14 + su] = hB2;
            shT[(n0+7)*14 + su] = hB3;

            if (t >= 30){
                float sum = hA0+hA1+hA2+hA3+hB0+hB1+hB2+hB3;
                float ssq = hA0*hA0+hA1*hA1+hA2*hA2+hA3*hA3
                          + hB0*hB0+hB1*hB1+hB2*hB2+hB3*hB3;
                #pragma unroll
                for (int o=8;o>=1;o>>=1){
                    sum += __shfl_xor_sync(0xffffffffu, sum, o, 16);
                    ssq += __shfl_xor_sync(0xffffffffu, ssq, o, 16);
                }
                float mean = sum*(1.f/128.f);
                float var  = ssq*(1.f/128.f) - mean*mean;
                float rstd = rsqrtf(var + 1e-5f);
                float4 oA, oB;
                oA.x = (hA0-mean)*rstd*gA4.x + bA4.x;
                oA.y = (hA1-mean)*rstd*gA4.y + bA4.y;
                oA.z = (hA2-mean)*rstd*gA4.z + bA4.z;
                oA.w = (hA3-mean)*rstd*gA4.w + bA4.w;
                oB.x = (hB0-mean)*rstd*gB4.x + bB4.x;
                oB.y = (hB1-mean)*rstd*gB4.y + bB4.y;
                oB.z = (hB2-mean)*rstd*gB4.z + bB4.z;
                oB.w = (hB3-mean)*rstd*gB4.w + bB4.w;
                float* dst = &g_Hln[((bs0+su)*10 + (t-30))*128 + n0];
                *(float4*)dst       = oA;
                *(float4*)(dst + 4) = oB;
            }
        }
    }
}

// ---------------- kernel 2: register-tiled projection + row l2norm ----------
// 64 rows x 128 cols per block, 256 threads (16x16), thread = 4 rows x 8 cols.
__global__ void __launch_bounds__(256) proj2_kernel(
    const float* __restrict__ W, const int* __restrict__ gatherIdx,
    int nrows, int which)
{
    extern __shared__ float ps[];
    float* sW  = ps;              // [128][132] k-major W^T
    float* sAT = ps + 128*132;    // [128][68]  k-major A tile
    float* out = which ? g_q : g_Hk;

    const int tid = threadIdx.x;
    const int tx  = tid & 15, ty = tid >> 4;
    const int r0  = blockIdx.x*64;

    for (int idx=tid; idx<128*32; idx+=256){
        int j = idx >> 5, kq = idx & 31;
        float4 v = *(const float4*)&W[j*128 + kq*4];
        sW[(kq*4+0)*132 + j] = v.x;
        sW[(kq*4+1)*132 + j] = v.y;
        sW[(kq*4+2)*132 + j] = v.z;
        sW[(kq*4+3)*132 + j] = v.w;
    }
    for (int idx=tid; idx<64*32; idx+=256){
        int r = idx >> 5, kq = idx & 31;
        int gr = r0 + r;
        float4 v = make_float4(0.f,0.f,0.f,0.f);
        if (gr < nrows){
            int src = gatherIdx ? (gatherIdx[gr]*10 + 9) : gr;
            v = *(const float4*)&g_Hln[src*128 + kq*4];
        }
        sAT[(kq*4+0)*68 + r] = v.x;
        sAT[(kq*4+1)*68 + r] = v.y;
        sAT[(kq*4+2)*68 + r] = v.z;
        sAT[(kq*4+3)*68 + r] = v.w;
    }
    __syncthreads();

    float accf[4][8];
    #pragma unroll
    for (int r=0;r<4;r++)
        #pragma unroll
        for (int c=0;c<8;c++) accf[r][c]=0.f;

    const float* arow = &sAT[ty*4];
    const float* wrow = &sW[tx*8];
    #pragma unroll 4
    for (int k=0;k<128;k++){
        float4 av = *(const float4*)&arow[k*68];
        float4 w0 = *(const float4*)&wrow[k*132];
        float4 w1 = *(const float4*)&wrow[k*132 + 4];
        const float wv[8] = {w0.x,w0.y,w0.z,w0.w,w1.x,w1.y,w1.z,w1.w};
        #pragma unroll
        for (int c=0;c<8;c++){
            accf[0][c] += av.x*wv[c];
            accf[1][c] += av.y*wv[c];
            accf[2][c] += av.z*wv[c];
            accf[3][c] += av.w*wv[c];
        }
    }

    #pragma unroll
    for (int r=0;r<4;r++){
        float ss=0.f;
        #pragma unroll
        for (int c=0;c<8;c++) ss += accf[r][c]*accf[r][c];
        #pragma unroll
        for (int o=8;o>=1;o>>=1) ss += __shfl_xor_sync(0xffffffffu, ss, o);
        float inv = 1.f/fmaxf(sqrtf(ss), 1e-12f);
        int gr = r0 + ty*4 + r;
        if (gr < nrows){
            float4 o0, o1;
            o0.x=accf[r][0]*inv; o0.y=accf[r][1]*inv; o0.z=accf[r][2]*inv; o0.w=accf[r][3]*inv;
            o1.x=accf[r][4]*inv; o1.y=accf[r][5]*inv; o1.z=accf[r][6]*inv; o1.w=accf[r][7]*inv;
            *(float4*)&out[gr*128 + tx*8]     = o0;
            *(float4*)&out[gr*128 + tx*8 + 4] = o1;
        }
    }
}

// ---------------- kernel 3: attention GEMM + fused top-5 --------------------
// 64x64 tiles, 4x4 micro-tile, double-buffered via __pipeline intrinsics.
__global__ void __launch_bounds__(256) attn2_kernel(
    const float* __restrict__ log_temp, const float* __restrict__ lag_bias,
    const int*   __restrict__ target_idx)
{
    extern __shared__ float smem[];
    float* sAT = smem;                   // [128][68]  k-major A
    float* sB0 = smem + 128*68;          // [64][128]  swizzled B buf 0
    float* sB1 = sB0 + 64*128;           // [64][128]  swizzled B buf 1
    __shared__ float slb[10];
    __shared__ float sinvt;

    const int tid = threadIdx.x;
    const int tx  = tid & 15, ty = tid >> 4;
    const int rbase = blockIdx.x*64;

    if (tid < 10) slb[tid] = lag_bias[tid];
    if (tid == 0){
        float tp = __expf(log_temp[0]);
        tp = fminf(fmaxf(tp, 0.1f), 11.313708498984761f);
        sinvt = 1.f/tp;
    }

    for (int idx = tid; idx < 64*32; idx += 256){
        int row = idx >> 5, kq = idx & 31;
        int gr = rbase + row;
        float4 v = make_float4(0.f,0.f,0.f,0.f);
        if (gr < S_) v = *(const float4*)&g_q[gr*128 + kq*4];
        sAT[(kq*4+0)*68 + row] = v.x;
        sAT[(kq*4+1)*68 + row] = v.y;
        sAT[(kq*4+2)*68 + row] = v.z;
        sAT[(kq*4+3)*68 + row] = v.w;
    }

    int myst[4];
    #pragma unroll
    for (int i=0;i<4;i++){
        int gr = rbase + ty*4 + i;
        myst[i] = (gr < S_) ? target_idx[gr] : -1;
    }

    float tv[4][5]; int ti[4][5];
    #pragma unroll
    for (int r=0;r<4;r++)
        #pragma unroll
        for (int p=0;p<5;p++){ tv[r][p] = -FLT_MAX; ti[r][p] = 0x7fffffff; }

    const int tstart = blockIdx.y*TILES_PER_SPLIT_;
    const int tend   = min(tstart+TILES_PER_SPLIT_, NTILE_);
    const int nt     = tend - tstart;
    const int swz    = tx & 7;

    auto load_tile = [&](float* sB, int tile){
        const int c0 = tile*64;
        for (int idx = tid; idx < 64*32; idx += 256){
            int col = idx >> 5, kq = idx & 31;
            int gc = c0 + col;
            bool v = (gc < SL_);
            const float* src = &g_Hk[(v ? gc : 0)*128 + kq*4];
            int ks = kq ^ ((col>>2)&7);
            __pipeline_memcpy_async(&sB[col*128 + ks*4], src, 16, v ? 0 : 16);
        }
        __pipeline_commit();
    };

    load_tile(sB0, tstart);
    if (nt > 1) load_tile(sB1, tstart+1);

    for (int i = 0; i < nt; i++){
        float* cur = (i & 1) ? sB1 : sB0;
        const int c0 = (tstart + i)*64;
        if (i+1 < nt) __pipeline_wait_prior(1);
        else          __pipeline_wait_prior(0);
        __syncthreads();

        float acc[4][4];
        #pragma unroll
        for (int r=0;r<4;r++)
            #pragma unroll
            for (int c=0;c<4;c++) acc[r][c]=0.f;

        const float* arow  = &sAT[ty*4];
        const float* bbase = &cur[(tx*4)*128];

        #pragma unroll 4
        for (int kb = 0; kb < 32; kb++){
            float4 Af[4];
            Af[0] = *(const float4*)&arow[(kb*4+0)*68];
            Af[1] = *(const float4*)&arow[(kb*4+1)*68];
            Af[2] = *(const float4*)&arow[(kb*4+2)*68];
            Af[3] = *(const float4*)&arow[(kb*4+3)*68];
            const int ks = (kb ^ swz)*4;
            float4 Bf[4];
            Bf[0] = *(const float4*)&bbase[0*128 + ks];
            Bf[1] = *(const float4*)&bbase[1*128 + ks];
            Bf[2] = *(const float4*)&bbase[2*128 + ks];
            Bf[3] = *(const float4*)&bbase[3*128 + ks];
            const float* av = (const float*)Af;   // av[k*4 + r]
            const float* bv = (const float*)Bf;   // bv[c*4 + k]
            #pragma unroll
            for (int r=0;r<4;r++)
                #pragma unroll
                for (int c=0;c<4;c++)
                    #pragma unroll
                    for (int k=0;k<4;k++)
                        acc[r][c] += av[k*4+r]*bv[c*4+k];
        }

        const float invt = sinvt;
        #pragma unroll
        for (int c=0;c<4;c++){
            int gc = c0 + tx*4 + c;
            int s  = gc/10;
            int l  = gc - s*10;
            bool colok = (gc < SL_);
            float lb = slb[l];
            #pragma unroll
            for (int r=0;r<4;r++){
                if (!colok || s == myst[r]) continue;
                float sc = acc[r][c]*invt + lb;
                if (better(sc, gc, tv[r][4], ti[r][4])){
                    tv[r][4]=sc; ti[r][4]=gc;
                    #pragma unroll
                    for (int p=4;p>0;p--){
                        if (better(tv[r][p],ti[r][p],tv[r][p-1],ti[r][p-1])){
                            float tvv=tv[r][p]; tv[r][p]=tv[r][p-1]; tv[r][p-1]=tvv;
                            int   tii=ti[r][p]; ti[r][p]=ti[r][p-1]; ti[r][p-1]=tii;
                        }
                    }
                }
            }
        }
        __syncthreads();
        if (i+2 < nt) load_tile(cur, tstart+i+2);
    }

    // Merge 16 partial top-5 lists per row (alias smem)
    __syncthreads();
    float* mv = smem;                         // [64][16][5] floats (20KB)
    int*   mi = (int*)(smem + 64*16*5);       // [64][16][5] ints   (20KB)
    #pragma unroll
    for (int r=0;r<4;r++){
        int row = ty*4+r;
        #pragma unroll
        for (int p=0;p<5;p++){
            mv[(row*16+tx)*5+p] = tv[r][p];
            mi[(row*16+tx)*5+p] = ti[r][p];
        }
    }
    __syncthreads();
    if (tid < 64){
        int gr = rbase + tid;
        if (gr < S_){
            float* cv = &mv[tid*80];
            int*   ci = &mi[tid*80];
            for (int kk=0;kk<5;kk++){
                float bv=-FLT_MAX; int bi=0x7fffffff; int bp=0;
                for (int m=0;m<80;m++){
                    if (better(cv[m],ci[m],bv,bi)){ bv=cv[m]; bi=ci[m]; bp=m; }
                }
                g_pval[gr*40 + blockIdx.y*5 + kk]=bv;
                g_pidx[gr*40 + blockIdx.y*5 + kk]=bi;
                cv[bp]=-FLT_MAX; ci[bp]=0x7fffffff;
            }
        }
    }
}

// ---------------- kernel 4: merge + softmax + gather + MLP -----------------
__global__ void __launch_bounds__(256) final_kernel(
    const float* __restrict__ Xraw,
    const float* __restrict__ W1, const float* __restrict__ b1,
    const float* __restrict__ W2, const float* __restrict__ b2,
    const float* __restrict__ W3, const float* __restrict__ b3,
    float* __restrict__ out)
{
    int t = blockIdx.x*256 + threadIdx.x;
    if (t >= S_) return;
    float cv[NS5_]; int ci[NS5_];
    #pragma unroll
    for (int m=0;m<NS5_;m++){ cv[m]=g_pval[t*40+m]; ci[m]=g_pidx[t*40+m]; }
    float v5[5]; int i5[5];
    #pragma unroll
    for (int kk=0;kk<5;kk++){
        float bv=-FLT_MAX; int bi=0x7fffffff; int bp=0;
        #pragma unroll
        for (int m=0;m<NS5_;m++)
            if (better(cv[m],ci[m],bv,bi)){ bv=cv[m]; bi=ci[m]; bp=m; }
        v5[kk]=bv; i5[kk]=bi;
        cv[bp]=-FLT_MAX; ci[bp]=0x7fffffff;
    }
    float w[5]; float den=0.f;
    #pragma unroll
    for (int kk=0;kk<5;kk++){ w[kk]=__expf(v5[kk]-v5[0]); den+=w[kk]; }
    float invden = 1.f/den;
    float feat[12];
    float zagg[6] = {0,0,0,0,0,0};
    #pragma unroll
    for (int kk=0;kk<5;kk++){
        int idx = i5[kk];
        int leader = idx/10;
        int lag    = idx - leader*10;
        int pos    = 29 + lag;
        const float* zp = &Xraw[(leader*40 + pos)*6];
        float ww = w[kk]*invden;
        #pragma unroll
        for (int f=0;f<6;f++){
            float zf = zp[f];
            zagg[f] += ww*zf;
            if (kk==0) feat[6+f]=zf;
        }
    }
    #pragma unroll
    for (int f=0;f<6;f++) feat[f]=zagg[f];

    float h1[64];
    #pragma unroll
    for (int j=0;j<64;j++){
        float a = b1[j];
        #pragma unroll
        for (int f=0;f<12;f++) a += W1[j*12+f]*feat[f];
        h1[j] = fmaxf(a,0.f);
    }
    float h2[32];
    #pragma unroll
    for (int j=0;j<32;j++){
        float a = b2[j];
        #pragma unroll
        for (int f=0;f<64;f++) a += W2[j*64+f]*h1[f];
        h2[j] = fmaxf(a,0.f);
    }
    float a = b3[0];
    #pragma unroll
    for (int j=0;j<32;j++) a += W3[j]*h2[j];
    out[t] = a;
}

// ---------------- launch ----------------------------------------------------
extern "C" void kernel_launch(void* const* d_in, const int* in_sizes, int n_in,
                              void* d_out, int out_size)
{
    const float* Xs  =(const float*)d_in[0];
    const float* Xr  =(const float*)d_in[1];
    const int*   tgt =(const int*)  d_in[2];
    const float* Wih =(const float*)d_in[3];
    const float* Whh =(const float*)d_in[4];
    const float* bihp=(const float*)d_in[5];
    const float* bhhp=(const float*)d_in[6];
    const float* lng =(const float*)d_in[7];
    const float* lnb =(const float*)d_in[8];
    const float* WQ  =(const float*)d_in[9];
    const float* WK  =(const float*)d_in[10];
    const float* logt=(const float*)d_in[11];
    const float* lagb=(const float*)d_in[12];
    const float* W1  =(const float*)d_in[13];
    const float* b1  =(const float*)d_in[14];
    const float* W2  =(const float*)d_in[15];
    const float* b2  =(const float*)d_in[16];
    const float* W3  =(const float*)d_in[17];
    const float* b3  =(const float*)d_in[18];
    float* out = (float*)d_out;

    const int attn_smem = (128*68 + 2*64*128) * (int)sizeof(float);  // 100352 B
    const int proj_smem = (128*132 + 128*68) * (int)sizeof(float);   // 102400 B
    cudaFuncSetAttribute(attn2_kernel, cudaFuncAttributeMaxDynamicSharedMemorySize, attn_smem);
    cudaFuncSetAttribute(proj2_kernel, cudaFuncAttributeMaxDynamicSharedMemorySize, proj_smem);

    pack_whh<<<128,256>>>(Whh);
    lstm_kernel<<<NBLK_,256>>>(Xs, Wih, bihp, bhhp, lng, lnb);
    proj2_kernel<<<469,256, proj_smem>>>(WK, nullptr, SL_, 0);   // -> g_Hk
    proj2_kernel<<<47, 256, proj_smem>>>(WQ, tgt,     S_,  1);   // -> g_q
    attn2_kernel<<<dim3(47,NSPLIT_),256, attn_smem>>>(logt, lagb, tgt);
    final_kernel<<<12,256>>>(Xr, W1,b1, W2,b2, W3,b3, out);
}

// round 13
// speedup vs baseline: 1.6257x; 1.0220x over previous
#include <cuda_runtime.h>
#include <cuda_pipeline.h>
#include <mma.h>
#include <math.h>
#include <float.h>

using namespace nvcuda;

#define S_    3000
#define F_    6
#define N_    128
#define L_    40
#define LMAX_ 10
#define K_    5
#define SL_   (S_*LMAX_)   // 30000
#define NTILE_ 469         // ceil(30000/64)
#define NSPLIT_ 6
#define TILES_PER_SPLIT_ 79
#define CPS_  8            // candidates kept per split
#define CAND_ (NSPLIT_*CPS_) // 48 candidates per target
#define NBLK_ 250          // LSTM blocks (12 stocks each)

// ---------------- scratch (device globals; no allocations allowed) ----------
__device__ float2 g_Whh2f[128*256];      // [k][j] = (Whh[2j][k], Whh[2j+1][k])
__device__ float  g_Hln[SL_*N_];         // [30000][128] layernormed H, t in [30,40)
__device__ float  g_Hk [SL_*N_];         // l2norm(Hln @ WK^T)
__device__ float  g_q  [S_*N_];          // l2norm(Hln[tgt,9] @ WQ^T)
__device__ float  g_pval[S_*CAND_];      // approx candidate scores (unused downstream)
__device__ int    g_pidx[S_*CAND_];      // candidate indices
__device__ float  g_exv[S_*K_];          // exact top-5 values
__device__ int    g_exi[S_*K_];          // exact top-5 indices

__device__ __forceinline__ float sigf(float x){ return 1.f/(1.f+__expf(-x)); }
__device__ __forceinline__ float tanhfast(float x){ return 2.f/(1.f+__expf(-2.f*x)) - 1.f; }
__device__ __forceinline__ bool better(float v,int i,float bv,int bi){
    return (v>bv) || (v==bv && i<bi);
}

// ---------------- kernel 0: pack Whh -> g_Whh2f[k*256+j] --------------------
__global__ void __launch_bounds__(256) pack_whh(const float* __restrict__ Whh){
    int idx = blockIdx.x*256 + threadIdx.x;          // 32768 elements
    if (idx < 128*256){
        int k = idx >> 8, j = idx & 255;
        g_Whh2f[idx] = make_float2(Whh[(2*j)*128 + k], Whh[(2*j+1)*128 + k]);
    }
}

// ---------------- kernel 1: LSTM (+ fused LayerNorm for t>=30) --------------
// (unchanged from round-12 pass)
__global__ void __launch_bounds__(256) lstm_kernel(
    const float* __restrict__ X,   const float* __restrict__ Wih,
    const float* __restrict__ bih, const float* __restrict__ bhh,
    const float* __restrict__ lng, const float* __restrict__ lnb)
{
    __shared__ float  shT[128*14];
    __shared__ float  sg[12][516];
    __shared__ float2 sx2[240*6];
    const int tid = threadIdx.x;
    const int bs0 = blockIdx.x*12;

    for (int idx = tid; idx < 240*6; idx += 256){
        int tf = idx/6, p = idx - (idx/6)*6;
        sx2[tf*6 + p] = make_float2(X[(bs0 + 2*p)*240 + tf],
                                    X[(bs0 + 2*p+1)*240 + tf]);
    }
    for (int idx = tid; idx < 128*14; idx += 256) shT[idx] = 0.f;

    const int j0 = tid*2;
    float wih0[6], wih1[6];
    #pragma unroll
    for (int f=0;f<6;f++){
        wih0[f] = Wih[(j0  )*6 + f];
        wih1[f] = Wih[(j0+1)*6 + f];
    }
    const float bb0 = bih[j0]   + bhh[j0];
    const float bb1 = bih[j0+1] + bhh[j0+1];

    const int su = tid >> 4;
    const int n0 = (tid & 15)*8;
    float4 cA = make_float4(0.f,0.f,0.f,0.f);
    float4 cB = make_float4(0.f,0.f,0.f,0.f);
    float4 gA4, gB4, bA4, bB4;
    if (su < 12){
        gA4 = *(const float4*)&lng[n0];   gB4 = *(const float4*)&lng[n0+4];
        bA4 = *(const float4*)&lnb[n0];   bB4 = *(const float4*)&lnb[n0+4];
    }

    for (int t=0; t<40; t++){
        __syncthreads();
        float a0x[6], a0y[6], a1x[6], a1y[6];
        #pragma unroll
        for (int p=0;p<6;p++){ a0x[p]=bb0; a0y[p]=bb0; a1x[p]=bb1; a1y[p]=bb1; }
        #pragma unroll
        for (int f=0;f<6;f++){
            float w0 = wih0[f], w1 = wih1[f];
            #pragma unroll
            for (int p=0;p<6;p++){
                float2 xp = sx2[(t*6+f)*6 + p];
                a0x[p] += xp.x*w0; a0y[p] += xp.y*w0;
                a1x[p] += xp.x*w1; a1y[p] += xp.y*w1;
            }
        }
        #pragma unroll 4
        for (int k=0; k<128; k++){
            float2 wf = g_Whh2f[k*256 + tid];
            #pragma unroll
            for (int p=0;p<6;p++){
                float2 hp = *(const float2*)&shT[k*14 + 2*p];
                a0x[p] += hp.x*wf.x; a0y[p] += hp.y*wf.x;
                a1x[p] += hp.x*wf.y; a1y[p] += hp.y*wf.y;
            }
        }
        #pragma unroll
        for (int p=0;p<6;p++){
            sg[2*p  ][j0  ] = a0x[p];
            sg[2*p+1][j0  ] = a0y[p];
            sg[2*p  ][j0+1] = a1x[p];
            sg[2*p+1][j0+1] = a1y[p];
        }
        __syncthreads();

        if (su < 12){
            float4 giA = *(const float4*)&sg[su][n0];
            float4 giB = *(const float4*)&sg[su][n0+4];
            float4 gfA = *(const float4*)&sg[su][128+n0];
            float4 gfB = *(const float4*)&sg[su][128+n0+4];
            float4 ggA = *(const float4*)&sg[su][256+n0];
            float4 ggB = *(const float4*)&sg[su][256+n0+4];
            float4 goA = *(const float4*)&sg[su][384+n0];
            float4 goB = *(const float4*)&sg[su][384+n0+4];

            cA.x = sigf(gfA.x)*cA.x + sigf(giA.x)*tanhfast(ggA.x);
            cA.y = sigf(gfA.y)*cA.y + sigf(giA.y)*tanhfast(ggA.y);
            cA.z = sigf(gfA.z)*cA.z + sigf(giA.z)*tanhfast(ggA.z);
            cA.w = sigf(gfA.w)*cA.w + sigf(giA.w)*tanhfast(ggA.w);
            cB.x = sigf(gfB.x)*cB.x + sigf(giB.x)*tanhfast(ggB.x);
            cB.y = sigf(gfB.y)*cB.y + sigf(giB.y)*tanhfast(ggB.y);
            cB.z = sigf(gfB.z)*cB.z + sigf(giB.z)*tanhfast(ggB.z);
            cB.w = sigf(gfB.w)*cB.w + sigf(giB.w)*tanhfast(ggB.w);

            float hA0 = sigf(goA.x)*tanhfast(cA.x);
            float hA1 = sigf(goA.y)*tanhfast(cA.y);
            float hA2 = sigf(goA.z)*tanhfast(cA.z);
            float hA3 = sigf(goA.w)*tanhfast(cA.w);
            float hB0 = sigf(goB.x)*tanhfast(cB.x);
            float hB1 = sigf(goB.y)*tanhfast(cB.y);
            float hB2 = sigf(goB.z)*tanhfast(cB.z);
            float hB3 = sigf(goB.w)*tanhfast(cB.w);

            shT[(n0+0)*14 + su] = hA0;
            shT[(n0+1)*14 + su] = hA1;
            shT[(n0+2)*14 + su] = hA2;
            shT[(n0+3)*14 + su] = hA3;
            shT[(n0+4)*14 + su] = hB0;
            shT[(n0+5)*14 + su] = hB1;
            shT[(n0+6)*14 + su] = hB2;
            shT[(n0+7)*14 + su] = hB3;

            if (t >= 30){
                float sum = hA0+hA1+hA2+hA3+hB0+hB1+hB2+hB3;
                float ssq = hA0*hA0+hA1*hA1+hA2*hA2+hA3*hA3
                          + hB0*hB0+hB1*hB1+hB2*hB2+hB3*hB3;
                #pragma unroll
                for (int o=8;o>=1;o>>=1){
                    sum += __shfl_xor_sync(0xffffffffu, sum, o, 16);
                    ssq += __shfl_xor_sync(0xffffffffu, ssq, o, 16);
                }
                float mean = sum*(1.f/128.f);
                float var  = ssq*(1.f/128.f) - mean*mean;
                float rstd = rsqrtf(var + 1e-5f);
                float4 oA, oB;
                oA.x = (hA0-mean)*rstd*gA4.x + bA4.x;
                oA.y = (hA1-mean)*rstd*gA4.y + bA4.y;
                oA.z = (hA2-mean)*rstd*gA4.z + bA4.z;
                oA.w = (hA3-mean)*rstd*gA4.w + bA4.w;
                oB.x = (hB0-mean)*rstd*gB4.x + bB4.x;
                oB.y = (hB1-mean)*rstd*gB4.y + bB4.y;
                oB.z = (hB2-mean)*rstd*gB4.z + bB4.z;
                oB.w = (hB3-mean)*rstd*gB4.w + bB4.w;
                float* dst = &g_Hln[((bs0+su)*10 + (t-30))*128 + n0];
                *(float4*)dst       = oA;
                *(float4*)(dst + 4) = oB;
            }
        }
    }
}

// ---------------- kernel 2: register-tiled projection + row l2norm ----------
// (unchanged from round-12 pass)
__global__ void __launch_bounds__(256) proj2_kernel(
    const float* __restrict__ W, const int* __restrict__ gatherIdx,
    int nrows, int which)
{
    extern __shared__ float ps[];
    float* sW  = ps;              // [128][132] k-major W^T
    float* sAT = ps + 128*132;    // [128][68]  k-major A tile
    float* out = which ? g_q : g_Hk;

    const int tid = threadIdx.x;
    const int tx  = tid & 15, ty = tid >> 4;
    const int r0  = blockIdx.x*64;

    for (int idx=tid; idx<128*32; idx+=256){
        int j = idx >> 5, kq = idx & 31;
        float4 v = *(const float4*)&W[j*128 + kq*4];
        sW[(kq*4+0)*132 + j] = v.x;
        sW[(kq*4+1)*132 + j] = v.y;
        sW[(kq*4+2)*132 + j] = v.z;
        sW[(kq*4+3)*132 + j] = v.w;
    }
    for (int idx=tid; idx<64*32; idx+=256){
        int r = idx >> 5, kq = idx & 31;
        int gr = r0 + r;
        float4 v = make_float4(0.f,0.f,0.f,0.f);
        if (gr < nrows){
            int src = gatherIdx ? (gatherIdx[gr]*10 + 9) : gr;
            v = *(const float4*)&g_Hln[src*128 + kq*4];
        }
        sAT[(kq*4+0)*68 + r] = v.x;
        sAT[(kq*4+1)*68 + r] = v.y;
        sAT[(kq*4+2)*68 + r] = v.z;
        sAT[(kq*4+3)*68 + r] = v.w;
    }
    __syncthreads();

    float accf[4][8];
    #pragma unroll
    for (int r=0;r<4;r++)
        #pragma unroll
        for (int c=0;c<8;c++) accf[r][c]=0.f;

    const float* arow = &sAT[ty*4];
    const float* wrow = &sW[tx*8];
    #pragma unroll 4
    for (int k=0;k<128;k++){
        float4 av = *(const float4*)&arow[k*68];
        float4 w0 = *(const float4*)&wrow[k*132];
        float4 w1 = *(const float4*)&wrow[k*132 + 4];
        const float wv[8] = {w0.x,w0.y,w0.z,w0.w,w1.x,w1.y,w1.z,w1.w};
        #pragma unroll
        for (int c=0;c<8;c++){
            accf[0][c] += av.x*wv[c];
            accf[1][c] += av.y*wv[c];
            accf[2][c] += av.z*wv[c];
            accf[3][c] += av.w*wv[c];
        }
    }

    #pragma unroll
    for (int r=0;r<4;r++){
        float ss=0.f;
        #pragma unroll
        for (int c=0;c<8;c++) ss += accf[r][c]*accf[r][c];
        #pragma unroll
        for (int o=8;o>=1;o>>=1) ss += __shfl_xor_sync(0xffffffffu, ss, o);
        float inv = 1.f/fmaxf(sqrtf(ss), 1e-12f);
        int gr = r0 + ty*4 + r;
        if (gr < nrows){
            float4 o0, o1;
            o0.x=accf[r][0]*inv; o0.y=accf[r][1]*inv; o0.z=accf[r][2]*inv; o0.w=accf[r][3]*inv;
            o1.x=accf[r][4]*inv; o1.y=accf[r][5]*inv; o1.z=accf[r][6]*inv; o1.w=accf[r][7]*inv;
            *(float4*)&out[gr*128 + tx*8]     = o0;
            *(float4*)&out[gr*128 + tx*8 + 4] = o1;
        }
    }
}

// ---------------- kernel 3: wmma tf32 attention + fused approx top-5 --------
// 64x64 tiles, 8 warps x two 16x16 tf32 fragments, double-buffered B.
// Keeps top-8 CANDIDATES per split per target (exact rescored later).
__global__ void __launch_bounds__(256) attn3_kernel(
    const float* __restrict__ log_temp, const float* __restrict__ lag_bias,
    const int*   __restrict__ target_idx)
{
    extern __shared__ float smem[];
    float* sA  = smem;              // [64][132] row-major q tile
    float* sB0 = smem + 64*132;     // [64 cols][132] (col-major B, ld=132)
    float* sB1 = sB0 + 64*132;
    __shared__ float slb[10];
    __shared__ float sinvt;

    const int tid  = threadIdx.x;
    const int tx   = tid & 15, ty = tid >> 4;
    const int warp = tid >> 5;
    const int rbase = blockIdx.x*64;

    if (tid < 10) slb[tid] = lag_bias[tid];
    if (tid == 0){
        float tp = __expf(log_temp[0]);
        tp = fminf(fmaxf(tp, 0.1f), 11.313708498984761f);
        sinvt = 1.f/tp;
    }

    // Load A tile row-major [64][132]
    for (int idx = tid; idx < 64*32; idx += 256){
        int row = idx >> 5, kq = idx & 31;
        int gr = rbase + row;
        float4 v = make_float4(0.f,0.f,0.f,0.f);
        if (gr < S_) v = *(const float4*)&g_q[gr*128 + kq*4];
        *(float4*)&sA[row*132 + kq*4] = v;
    }

    int myst[4];
    #pragma unroll
    for (int i=0;i<4;i++){
        int gr = rbase + ty*4 + i;
        myst[i] = (gr < S_) ? target_idx[gr] : -1;
    }

    float tv[4][5]; int ti[4][5];
    #pragma unroll
    for (int r=0;r<4;r++)
        #pragma unroll
        for (int p=0;p<5;p++){ tv[r][p] = -FLT_MAX; ti[r][p] = 0x7fffffff; }

    const int tstart = blockIdx.y*TILES_PER_SPLIT_;
    const int tend   = min(tstart+TILES_PER_SPLIT_, NTILE_);
    const int nt     = tend - tstart;

    auto load_tile = [&](float* sB, int tile){
        const int c0 = tile*64;
        for (int idx = tid; idx < 64*32; idx += 256){
            int col = idx >> 5, kq = idx & 31;
            int gc = c0 + col;
            bool v = (gc < SL_);
            const float* src = &g_Hk[(v ? gc : 0)*128 + kq*4];
            __pipeline_memcpy_async(&sB[col*132 + kq*4], src, 16, v ? 0 : 16);
        }
        __pipeline_commit();
    };

    load_tile(sB0, tstart);
    if (nt > 1) load_tile(sB1, tstart+1);

    const int wr  = warp >> 1;          // 0..3: 16-row strip
    const int wc2 = warp & 1;           // 0..1: 32-col strip

    for (int i = 0; i < nt; i++){
        float* cur = (i & 1) ? sB1 : sB0;
        const int c0 = (tstart + i)*64;
        if (i+1 < nt) __pipeline_wait_prior(1);
        else          __pipeline_wait_prior(0);
        __syncthreads();

        wmma::fragment<wmma::accumulator,16,16,8,float> cf0, cf1;
        wmma::fill_fragment(cf0, 0.f);
        wmma::fill_fragment(cf1, 0.f);

        #pragma unroll 4
        for (int kt = 0; kt < 16; kt++){
            wmma::fragment<wmma::matrix_a,16,16,8,wmma::precision::tf32,wmma::row_major> af;
            wmma::fragment<wmma::matrix_b,16,16,8,wmma::precision::tf32,wmma::col_major> bf0, bf1;
            wmma::load_matrix_sync(af, &sA[wr*16*132 + kt*8], 132);
            #pragma unroll
            for (int e=0;e<af.num_elements;e++) af.x[e] = wmma::__float_to_tf32(af.x[e]);
            wmma::load_matrix_sync(bf0, &cur[(wc2*32)*132 + kt*8], 132);
            wmma::load_matrix_sync(bf1, &cur[(wc2*32+16)*132 + kt*8], 132);
            #pragma unroll
            for (int e=0;e<bf0.num_elements;e++) bf0.x[e] = wmma::__float_to_tf32(bf0.x[e]);
            #pragma unroll
            for (int e=0;e<bf1.num_elements;e++) bf1.x[e] = wmma::__float_to_tf32(bf1.x[e]);
            wmma::mma_sync(cf0, af, bf0, cf0);
            wmma::mma_sync(cf1, af, bf1, cf1);
        }

        __syncthreads();                  // all warps done reading cur
        float* scores = cur;              // alias scores [64][68] over cur
        wmma::store_matrix_sync(&scores[wr*16*68 + wc2*32],      cf0, 68, wmma::mem_row_major);
        wmma::store_matrix_sync(&scores[wr*16*68 + wc2*32 + 16], cf1, 68, wmma::mem_row_major);
        __syncthreads();

        const float invt = sinvt;
        #pragma unroll
        for (int c=0;c<4;c++){
            int gc = c0 + tx*4 + c;
            int s  = gc/10;
            int l  = gc - s*10;
            bool colok = (gc < SL_);
            float lb = slb[l];
            #pragma unroll
            for (int r=0;r<4;r++){
                if (!colok || s == myst[r]) continue;
                float sc = scores[(ty*4+r)*68 + tx*4+c]*invt + lb;
                if (better(sc, gc, tv[r][4], ti[r][4])){
                    tv[r][4]=sc; ti[r][4]=gc;
                    #pragma unroll
                    for (int p=4;p>0;p--){
                        if (better(tv[r][p],ti[r][p],tv[r][p-1],ti[r][p-1])){
                            float tvv=tv[r][p]; tv[r][p]=tv[r][p-1]; tv[r][p-1]=tvv;
                            int   tii=ti[r][p]; ti[r][p]=ti[r][p-1]; ti[r][p-1]=tii;
                        }
                    }
                }
            }
        }
        __syncthreads();                  // scans done before cur is overwritten
        if (i+2 < nt) load_tile(cur, tstart+i+2);
    }

    // Merge 16 partial top-5 lists per row -> top-8 candidates per split
    __syncthreads();
    float* mv = smem;                         // [64][16][5] floats (20KB)
    int*   mi = (int*)(smem + 64*16*5);       // [64][16][5] ints   (20KB)
    #pragma unroll
    for (int r=0;r<4;r++){
        int row = ty*4+r;
        #pragma unroll
        for (int p=0;p<5;p++){
            mv[(row*16+tx)*5+p] = tv[r][p];
            mi[(row*16+tx)*5+p] = ti[r][p];
        }
    }
    __syncthreads();
    if (tid < 64){
        int gr = rbase + tid;
        if (gr < S_){
            float* cv = &mv[tid*80];
            int*   ci = &mi[tid*80];
            for (int kk=0;kk<CPS_;kk++){
                float bv=-FLT_MAX; int bi=0x7fffffff; int bp=0;
                for (int m=0;m<80;m++){
                    if (better(cv[m],ci[m],bv,bi)){ bv=cv[m]; bi=ci[m]; bp=m; }
                }
                g_pval[gr*CAND_ + blockIdx.y*CPS_ + kk]=bv;
                g_pidx[gr*CAND_ + blockIdx.y*CPS_ + kk]=bi;
                cv[bp]=-FLT_MAX; ci[bp]=0x7fffffff;
            }
        }
    }
}

// ---------------- kernel 3b: exact fp32 rescore of 48 candidates ------------
// One warp per target; lanes split the 128-dim dot.
__global__ void __launch_bounds__(256) rescore_kernel(
    const float* __restrict__ log_temp, const float* __restrict__ lag_bias)
{
    const int w    = blockIdx.x*8 + (threadIdx.x >> 5);   // target, 0..2999
    const int lane = threadIdx.x & 31;

    float tp = __expf(log_temp[0]);
    tp = fminf(fmaxf(tp, 0.1f), 11.313708498984761f);
    const float invt = 1.f/tp;

    float4 qv = *(const float4*)&g_q[w*128 + lane*4];

    float v5[5]; int i5[5];
    #pragma unroll
    for (int p=0;p<5;p++){ v5[p]=-FLT_MAX; i5[p]=0x7fffffff; }

    for (int c=0;c<CAND_;c++){
        int idx = g_pidx[w*CAND_ + c];
        float sc = -FLT_MAX;
        if ((unsigned)idx < (unsigned)SL_){
            float4 hv = *(const float4*)&g_Hk[idx*128 + lane*4];
            float p = qv.x*hv.x + qv.y*hv.y + qv.z*hv.z + qv.w*hv.w;
            #pragma unroll
            for (int o=16;o>=1;o>>=1) p += __shfl_xor_sync(0xffffffffu, p, o);
            int l = idx - (idx/10)*10;
            sc = p*invt + lag_bias[l];
        }
        if (better(sc, idx, v5[4], i5[4])){
            v5[4]=sc; i5[4]=idx;
            #pragma unroll
            for (int p=4;p>0;p--){
                if (better(v5[p],i5[p],v5[p-1],i5[p-1])){
                    float tvv=v5[p]; v5[p]=v5[p-1]; v5[p-1]=tvv;
                    int   tii=i5[p]; i5[p]=i5[p-1]; i5[p-1]=tii;
                }
            }
        }
    }
    if (lane == 0){
        #pragma unroll
        for (int p=0;p<5;p++){
            g_exv[w*5+p] = v5[p];
            g_exi[w*5+p] = i5[p];
        }
    }
}

// ---------------- kernel 4: softmax + gather + MLP --------------------------
__global__ void __launch_bounds__(256) final_kernel(
    const float* __restrict__ Xraw,
    const float* __restrict__ W1, const float* __restrict__ b1,
    const float* __restrict__ W2, const float* __restrict__ b2,
    const float* __restrict__ W3, const float* __restrict__ b3,
    float* __restrict__ out)
{
    int t = blockIdx.x*256 + threadIdx.x;
    if (t >= S_) return;
    float v5[5]; int i5[5];
    #pragma unroll
    for (int kk=0;kk<5;kk++){ v5[kk]=g_exv[t*5+kk]; i5[kk]=g_exi[t*5+kk]; }

    float w[5]; float den=0.f;
    #pragma unroll
    for (int kk=0;kk<5;kk++){ w[kk]=__expf(v5[kk]-v5[0]); den+=w[kk]; }
    float invden = 1.f/den;
    float feat[12];
    float zagg[6] = {0,0,0,0,0,0};
    #pragma unroll
    for (int kk=0;kk<5;kk++){
        int idx = i5[kk];
        int leader = idx/10;
        int lag    = idx - leader*10;
        int pos    = 29 + lag;
        const float* zp = &Xraw[(leader*40 + pos)*6];
        float ww = w[kk]*invden;
        #pragma unroll
        for (int f=0;f<6;f++){
            float zf = zp[f];
            zagg[f] += ww*zf;
            if (kk==0) feat[6+f]=zf;
        }
    }
    #pragma unroll
    for (int f=0;f<6;f++) feat[f]=zagg[f];

    float h1[64];
    #pragma unroll
    for (int j=0;j<64;j++){
        float a = b1[j];
        #pragma unroll
        for (int f=0;f<12;f++) a += W1[j*12+f]*feat[f];
        h1[j] = fmaxf(a,0.f);
    }
    float h2[32];
    #pragma unroll
    for (int j=0;j<32;j++){
        float a = b2[j];
        #pragma unroll
        for (int f=0;f<64;f++) a += W2[j*64+f]*h1[f];
        h2[j] = fmaxf(a,0.f);
    }
    float a = b3[0];
    #pragma unroll
    for (int j=0;j<32;j++) a += W3[j]*h2[j];
    out[t] = a;
}

// ---------------- launch ----------------------------------------------------
extern "C" void kernel_launch(void* const* d_in, const int* in_sizes, int n_in,
                              void* d_out, int out_size)
{
    const float* Xs  =(const float*)d_in[0];
    const float* Xr  =(const float*)d_in[1];
    const int*   tgt =(const int*)  d_in[2];
    const float* Wih =(const float*)d_in[3];
    const float* Whh =(const float*)d_in[4];
    const float* bihp=(const float*)d_in[5];
    const float* bhhp=(const float*)d_in[6];
    const float* lng =(const float*)d_in[7];
    const float* lnb =(const float*)d_in[8];
    const float* WQ  =(const float*)d_in[9];
    const float* WK  =(const float*)d_in[10];
    const float* logt=(const float*)d_in[11];
    const float* lagb=(const float*)d_in[12];
    const float* W1  =(const float*)d_in[13];
    const float* b1  =(const float*)d_in[14];
    const float* W2  =(const float*)d_in[15];
    const float* b2  =(const float*)d_in[16];
    const float* W3  =(const float*)d_in[17];
    const float* b3  =(const float*)d_in[18];
    float* out = (float*)d_out;

    const int attn_smem = (64*132 + 2*64*132) * (int)sizeof(float);  // 101376 B
    const int proj_smem = (128*132 + 128*68) * (int)sizeof(float);   // 102400 B
    cudaFuncSetAttribute(attn3_kernel, cudaFuncAttributeMaxDynamicSharedMemorySize, attn_smem);
    cudaFuncSetAttribute(proj2_kernel, cudaFuncAttributeMaxDynamicSharedMemorySize, proj_smem);

    pack_whh<<<128,256>>>(Whh);
    lstm_kernel<<<NBLK_,256>>>(Xs, Wih, bihp, bhhp, lng, lnb);
    proj2_kernel<<<469,256, proj_smem>>>(WK, nullptr, SL_, 0);   // -> g_Hk
    proj2_kernel<<<47, 256, proj_smem>>>(WQ, tgt,     S_,  1);   // -> g_q
    attn3_kernel<<<dim3(47,NSPLIT_),256, attn_smem>>>(logt, lagb, tgt);
    rescore_kernel<<<375,256>>>(logt, lagb);
    final_kernel<<<12,256>>>(Xr, W1,b1, W2,b2, W3,b3, out);
}